// round 1
// baseline (speedup 1.0000x reference)
#include <cuda_runtime.h>
#include <math.h>
#include <stdint.h>

// ---------------- problem constants ----------------
constexpr int cB  = 2;
constexpr int cL  = 4096;
constexpr int cD  = 1024;   // D_MODEL
constexpr int cKD = 768;    // KEY_DIM
constexpr int cVD = 1536;   // VALUE_DIM
constexpr int cH  = 8;
constexpr int cDK = 96;     // per-head qk dim
constexpr int cDV = 192;    // per-head v dim
constexpr int cCS = 64;     // chunk size
constexpr int cNC = cL / cCS;       // 64 chunks per sequence
constexpr int cM  = cB * cL;        // 8192 tokens
constexpr int cBH = cB * cH;        // 16

// ---------------- scratch (device globals; no cudaMalloc allowed) ----------------
__device__ float g_qc [cM * cKD];
__device__ float g_kc [cM * cKD];
__device__ float g_vc [cM * cVD];
__device__ float g_g  [cM * cVD];
__device__ float g_cq [cM * cKD];
__device__ float g_ck [cM * cKD];
__device__ float g_cv [cM * cVD];
__device__ float g_qn [cM * cKD];   // head layout; becomes qe after chunk_pre
__device__ float g_kn [cM * cKD];   // head layout; becomes kd after chunk_pre
__device__ float g_vh [cM * cVD];   // head layout; becomes u_ after chunk_pre
__device__ float g_kce[cM * cKD];   // kcd * exp(dec)
__device__ float g_gk [cBH * cL];
__device__ float g_bt [cBH * cL];
__device__ float g_at [cBH * cNC * cCS * cCS];  // intra-chunk attn
__device__ float g_edl[cBH * cNC];
__device__ float g_o  [cM * cVD];   // (b,h,l,dv)
__device__ float g_on [cM * cVD];   // (b,l,h*dv) gated+normed

// ---------------- generic SGEMM: C[M,N] = A[M,K] @ B[K,N], all row-major ----------------
// M%128==0, N%128==0, K%8==0 for all uses here.
__global__ void sgemm_kernel(const float* __restrict__ A, const float* __restrict__ B,
                             float* __restrict__ C, int M, int N, int K)
{
    __shared__ float As[8][128];
    __shared__ float Bs[8][128];
    const int tid = threadIdx.x;
    const int bm = blockIdx.y * 128;
    const int bn = blockIdx.x * 128;

    const int a_row = tid >> 1;          // 0..127
    const int a_col = (tid & 1) * 4;     // 0 or 4
    const int b_row = tid >> 5;          // 0..7
    const int b_col = (tid & 31) * 4;    // 0..124

    const int ty = tid >> 4;             // 0..15
    const int tx = tid & 15;             // 0..15

    float acc[8][8];
#pragma unroll
    for (int i = 0; i < 8; i++)
#pragma unroll
        for (int j = 0; j < 8; j++) acc[i][j] = 0.f;

    for (int k0 = 0; k0 < K; k0 += 8) {
        float4 av = *(const float4*)(A + (size_t)(bm + a_row) * K + k0 + a_col);
        As[a_col + 0][a_row] = av.x;
        As[a_col + 1][a_row] = av.y;
        As[a_col + 2][a_row] = av.z;
        As[a_col + 3][a_row] = av.w;
        float4 bv = *(const float4*)(B + (size_t)(k0 + b_row) * N + bn + b_col);
        *(float4*)&Bs[b_row][b_col] = bv;
        __syncthreads();
#pragma unroll
        for (int kk = 0; kk < 8; kk++) {
            float ra[8], rb[8];
#pragma unroll
            for (int i = 0; i < 8; i++) ra[i] = As[kk][ty * 8 + i];
#pragma unroll
            for (int j = 0; j < 8; j++) rb[j] = Bs[kk][tx * 8 + j];
#pragma unroll
            for (int i = 0; i < 8; i++)
#pragma unroll
                for (int j = 0; j < 8; j++) acc[i][j] += ra[i] * rb[j];
        }
        __syncthreads();
    }
#pragma unroll
    for (int i = 0; i < 8; i++) {
        float4* cp = (float4*)(C + (size_t)(bm + ty * 8 + i) * N + bn + tx * 8);
        cp[0] = make_float4(acc[i][0], acc[i][1], acc[i][2], acc[i][3]);
        cp[1] = make_float4(acc[i][4], acc[i][5], acc[i][6], acc[i][7]);
    }
}

// ---------------- gk / beta small projections + nonlinearity ----------------
__global__ void proj_gates_kernel(const float* __restrict__ u, const float* __restrict__ Wgk,
                                  const float* __restrict__ Wb, const float* __restrict__ b_b,
                                  const float* __restrict__ A_log, const float* __restrict__ dt_bias)
{
    int idx = blockIdx.x * blockDim.x + threadIdx.x;
    if (idx >= cM * cH) return;
    int m = idx / cH, h = idx % cH;
    const float* ur = u + (size_t)m * cD;
    float s1 = 0.f, s2 = 0.f;
    for (int i = 0; i < cD; i++) {
        float uv = ur[i];
        s1 += uv * Wgk[i * cH + h];
        s2 += uv * Wb [i * cH + h];
    }
    float x  = s1 + dt_bias[h];
    float sp = (x > 20.f) ? x : log1pf(expf(x));
    float gkv = -expf(A_log[h]) * sp;
    float bv  = 1.f / (1.f + expf(-(s2 + b_b[h])));
    int b = m / cL, l = m % cL;
    size_t o = ((size_t)(b * cH + h)) * cL + l;
    g_gk[o] = gkv;
    g_bt[o] = bv;
}

// ---------------- causal depthwise conv (K=4) + SiLU ----------------
__global__ void conv_silu_kernel(const float* __restrict__ x, const float* __restrict__ w,
                                 float* __restrict__ y, int C)
{
    int idx = blockIdx.x * blockDim.x + threadIdx.x;
    if (idx >= cM * C) return;
    int c = idx % C;
    int m = idx / C;
    int l = m % cL;
    float acc = 0.f;
#pragma unroll
    for (int j = 0; j < 4; j++) {
        int ll = l - 3 + j;
        if (ll >= 0) acc += x[(size_t)(m - l + ll) * C + c] * w[c * 4 + j];
    }
    y[idx] = acc / (1.f + expf(-acc));
}

// ---------------- L2 norm q,k + reshape to head layout ----------------
__global__ void l2norm_qk_kernel()
{
    int gw = (blockIdx.x * blockDim.x + threadIdx.x) >> 5;
    int lane = threadIdx.x & 31;
    if (gw >= 2 * cM * cH) return;
    int t = gw & 1;
    int rest = gw >> 1;
    int h = rest % cH;
    int m = rest / cH;
    const float* src = (t ? g_ck : g_cq) + (size_t)m * cKD + h * cDK;
    float v0 = src[lane], v1 = src[lane + 32], v2 = src[lane + 64];
    float ss = v0 * v0 + v1 * v1 + v2 * v2;
#pragma unroll
    for (int o = 16; o; o >>= 1) ss += __shfl_xor_sync(0xffffffffu, ss, o);
    float nrm = sqrtf(ss);
    float inv = 1.f / fmaxf(nrm, 1e-12f);
    int b = m / cL, l = m % cL;
    float* dst = (t ? g_kn : g_qn) + ((size_t)(b * cH + h) * cL + l) * cDK;
    dst[lane]      = v0 * inv;
    dst[lane + 32] = v1 * inv;
    dst[lane + 64] = v2 * inv;
}

// ---------------- v reshape to head layout ----------------
__global__ void reshape_v_kernel()
{
    int idx = blockIdx.x * blockDim.x + threadIdx.x;
    if (idx >= cM * cVD) return;
    int c = idx % cVD;
    int m = idx / cVD;
    int h = c / cDV, d = c % cDV;
    int b = m / cL, l = m % cL;
    g_vh[((size_t)(b * cH + h) * cL + l) * cDV + d] = g_cv[idx];
}

// ---------------- per-chunk precompute ----------------
// smem: sq(6144) sk(6144) skb(6144) sKK(4096) sM(4096) sv(12288) sdec(64) sbeta(64)
constexpr int CP_SMEM_FLOATS = 3 * 6144 + 4096 + 4096 + 12288 + 64 + 64;
__global__ void chunk_pre_kernel()
{
    extern __shared__ float sm[];
    float* sq   = sm;
    float* sk   = sq + 6144;
    float* skb  = sk + 6144;
    float* sKK  = skb + 6144;
    float* sM   = sKK + 4096;
    float* sv   = sM + 4096;
    float* sdec = sv + 12288;
    float* sbet = sdec + 64;

    const int tid = threadIdx.x;
    const int cid = blockIdx.x;           // 0..1023
    const int bh = cid / cNC;
    const int n  = cid % cNC;
    const size_t cbg  = (size_t)bh * cL + n * cCS;
    const size_t cb96  = cbg * cDK;
    const size_t cb192 = cbg * cDV;
    const float scale = rsqrtf((float)cDK);

    for (int i = tid; i < 6144; i += 256) { sq[i] = g_qn[cb96 + i]; sk[i] = g_kn[cb96 + i]; }
    if (tid < 64) sbet[tid] = g_bt[cbg + tid];
    __syncthreads();
    if (tid == 0) {
        float s = 0.f;
        for (int i = 0; i < 64; i++) { s += g_gk[cbg + i]; sdec[i] = s; }
    }
    __syncthreads();
    const float dl = sdec[63];

    for (int i = tid; i < 6144; i += 256)  skb[i] = sk[i] * sbet[i / cDK];
    for (int i = tid; i < 12288; i += 256) sv[i]  = g_vh[cb192 + i] * sbet[i / cDV];

    // write qe and kd back in place (shared copies keep originals)
    for (int i = tid; i < 6144; i += 256) {
        int c = i / cDK;
        g_qn[cb96 + i] = sq[i] * scale * expf(sdec[c]);
        g_kn[cb96 + i] = sk[i] * expf(dl - sdec[c]);
    }
    __syncthreads();

    // KK = kb @ k^T
    for (int idx = tid; idx < 4096; idx += 256) {
        int i = idx >> 6, j = idx & 63;
        float s = 0.f;
#pragma unroll 4
        for (int d = 0; d < cDK; d++) s += skb[i * cDK + d] * sk[j * cDK + d];
        sKK[idx] = s;
    }
    // intra-chunk attn (incl diagonal)
    for (int idx = tid; idx < 4096; idx += 256) {
        int i = idx >> 6, j = idx & 63;
        float a = 0.f;
        if (i >= j) {
            float s = 0.f;
#pragma unroll 4
            for (int d = 0; d < cDK; d++) s += sq[i * cDK + d] * sk[j * cDK + d];
            a = s * scale * expf(sdec[i] - sdec[j]);
        }
        g_at[(size_t)cid * 4096 + idx] = a;
    }
    // M1 = KK * Lmask, strict lower
    for (int idx = tid; idx < 4096; idx += 256) {
        int i = idx >> 6, j = idx & 63;
        sM[idx] = (i > j) ? sKK[idx] * expf(sdec[i] - sdec[j]) : 0.f;
    }
    __syncthreads();

    // forward substitution: u_ = M1^{-1} v   (in place in sv, 192 cols)
    for (int i = 1; i < 64; i++) {
        if (tid < 192) {
            float s = 0.f;
            for (int j = 0; j < i; j++) s += sM[i * 64 + j] * sv[j * 192 + tid];
            sv[i * 192 + tid] -= s;
        }
        __syncthreads();
    }
    // forward substitution: kcd = M2^{-1} kb  (M2 strict lower = KK; in place in skb, 96 cols)
    for (int i = 1; i < 64; i++) {
        if (tid < 96) {
            float s = 0.f;
            for (int j = 0; j < i; j++) s += sKK[i * 64 + j] * skb[j * 96 + tid];
            skb[i * 96 + tid] -= s;
        }
        __syncthreads();
    }

    for (int i = tid; i < 12288; i += 256) g_vh[cb192 + i] = sv[i];
    for (int i = tid; i < 6144; i += 256) {
        int c = i / cDK;
        g_kce[cb96 + i] = skb[i] * expf(sdec[c]);
    }
    if (tid == 0) g_edl[cid] = expf(dl);
}

// ---------------- sequential scan over chunks ----------------
// grid (6, 16): x = 32-wide value-column split, y = bh
constexpr int SC_SMEM_FLOATS = 3 * 6144 + 4096 + 2048 + 2048 + 3072;
__global__ void scan_kernel()
{
    extern __shared__ float sm[];
    float* sqe  = sm;
    float* skce = sqe + 6144;
    float* skd  = skce + 6144;
    float* sat  = skd + 6144;
    float* su   = sat + 4096;
    float* svn  = su + 2048;
    float* S    = svn + 2048;   // 96 x 32

    const int tid = threadIdx.x;
    const int bh = blockIdx.y;
    const int e0 = blockIdx.x * 32;
    const int e  = tid & 31;
    const int c0 = (tid >> 5) * 8;
    const int d0 = (tid >> 5) * 12;

    for (int i = tid; i < 3072; i += 256) S[i] = 0.f;

    for (int n = 0; n < cNC; n++) {
        const size_t cbg = (size_t)bh * cL + n * cCS;
        const size_t cb96 = cbg * cDK;
        const size_t cb192 = cbg * cDV;
        __syncthreads();
        for (int i = tid; i < 6144; i += 256) {
            sqe[i]  = g_qn[cb96 + i];
            skce[i] = g_kce[cb96 + i];
            skd[i]  = g_kn[cb96 + i];
        }
        for (int i = tid; i < 4096; i += 256)
            sat[i] = g_at[(size_t)(bh * cNC + n) * 4096 + i];
        for (int i = tid; i < 2048; i += 256) {
            int c = i >> 5, ee = i & 31;
            su[i] = g_vh[cb192 + (size_t)c * cDV + e0 + ee];
        }
        __syncthreads();

        // v_new = u - kce @ S
        float acc[8];
#pragma unroll
        for (int i = 0; i < 8; i++) acc[i] = 0.f;
        for (int j = 0; j < cDK; j++) {
            float sj = S[j * 32 + e];
#pragma unroll
            for (int i = 0; i < 8; i++) acc[i] += skce[(c0 + i) * cDK + j] * sj;
        }
#pragma unroll
        for (int i = 0; i < 8; i++) svn[(c0 + i) * 32 + e] = su[(c0 + i) * 32 + e] - acc[i];
        __syncthreads();

        // o = qe @ S + attn @ v_new
#pragma unroll
        for (int i = 0; i < 8; i++) acc[i] = 0.f;
        for (int j = 0; j < cDK; j++) {
            float sj = S[j * 32 + e];
#pragma unroll
            for (int i = 0; i < 8; i++) acc[i] += sqe[(c0 + i) * cDK + j] * sj;
        }
        for (int j = 0; j < 64; j++) {
            float vj = svn[j * 32 + e];
#pragma unroll
            for (int i = 0; i < 8; i++) acc[i] += sat[(c0 + i) * 64 + j] * vj;
        }
#pragma unroll
        for (int i = 0; i < 8; i++)
            g_o[cb192 + (size_t)(c0 + i) * cDV + e0 + e] = acc[i];
        __syncthreads();

        // S = S*exp(dl) + kd^T @ v_new
        const float el = g_edl[bh * cNC + n];
        float accS[12];
#pragma unroll
        for (int ii = 0; ii < 12; ii++) accS[ii] = 0.f;
        for (int c = 0; c < 64; c++) {
            float v = svn[c * 32 + e];
#pragma unroll
            for (int ii = 0; ii < 12; ii++) accS[ii] += skd[c * cDK + d0 + ii] * v;
        }
#pragma unroll
        for (int ii = 0; ii < 12; ii++) {
            int idx = (d0 + ii) * 32 + e;
            S[idx] = S[idx] * el + accS[ii];
        }
    }
}

// ---------------- gated RMS norm + transpose back ----------------
__global__ void gate_norm_kernel(const float* __restrict__ norm_w)
{
    int gw = (blockIdx.x * blockDim.x + threadIdx.x) >> 5;
    int lane = threadIdx.x & 31;
    if (gw >= cM * cH) return;
    int m = gw / cH, h = gw % cH;
    int b = m / cL, l = m % cL;
    const float* orow = g_o + ((size_t)(b * cH + h) * cL + l) * cDV;
    float vals[6];
    float ss = 0.f;
#pragma unroll
    for (int k = 0; k < 6; k++) {
        float v = orow[lane + 32 * k];
        vals[k] = v;
        ss += v * v;
    }
#pragma unroll
    for (int o = 16; o; o >>= 1) ss += __shfl_xor_sync(0xffffffffu, ss, o);
    float r = 1.f / sqrtf(ss / (float)cDV + 1e-5f);
#pragma unroll
    for (int k = 0; k < 6; k++) {
        int d = lane + 32 * k;
        size_t gi = (size_t)m * cVD + h * cDV + d;
        float gg = g_g[gi];
        float sg = gg / (1.f + expf(-gg));
        g_on[gi] = vals[k] * r * norm_w[d] * sg;
    }
}

// ---------------- host launch ----------------
static float* sym(const void* symbol)
{
    void* p = nullptr;
    cudaGetSymbolAddress(&p, symbol);
    return (float*)p;
}

extern "C" void kernel_launch(void* const* d_in, const int* in_sizes, int n_in,
                              void* d_out, int out_size)
{
    const float* u       = (const float*)d_in[0];
    const float* Wq      = (const float*)d_in[1];
    const float* Wk      = (const float*)d_in[2];
    const float* Wv      = (const float*)d_in[3];
    const float* Wg      = (const float*)d_in[4];
    const float* Wo      = (const float*)d_in[5];
    const float* Wgk     = (const float*)d_in[6];
    const float* Wb      = (const float*)d_in[7];
    const float* b_b     = (const float*)d_in[8];
    const float* A_log   = (const float*)d_in[9];
    const float* dt_bias = (const float*)d_in[10];
    const float* conv_q  = (const float*)d_in[11];
    const float* conv_k  = (const float*)d_in[12];
    const float* conv_v  = (const float*)d_in[13];
    const float* norm_w  = (const float*)d_in[14];
    float* out = (float*)d_out;

    float* qc = sym(g_qc); float* kc = sym(g_kc); float* vc = sym(g_vc); float* gg = sym(g_g);
    float* cq = sym(g_cq); float* ck = sym(g_ck); float* cv = sym(g_cv);
    float* on = sym(g_on);

    cudaFuncSetAttribute(chunk_pre_kernel, cudaFuncAttributeMaxDynamicSharedMemorySize,
                         CP_SMEM_FLOATS * (int)sizeof(float));
    cudaFuncSetAttribute(scan_kernel, cudaFuncAttributeMaxDynamicSharedMemorySize,
                         SC_SMEM_FLOATS * (int)sizeof(float));

    // projections
    sgemm_kernel<<<dim3(cKD / 128, cM / 128), 256>>>(u, Wq, qc, cM, cKD, cD);
    sgemm_kernel<<<dim3(cKD / 128, cM / 128), 256>>>(u, Wk, kc, cM, cKD, cD);
    sgemm_kernel<<<dim3(cVD / 128, cM / 128), 256>>>(u, Wv, vc, cM, cVD, cD);
    sgemm_kernel<<<dim3(cVD / 128, cM / 128), 256>>>(u, Wg, gg, cM, cVD, cD);
    proj_gates_kernel<<<(cM * cH + 255) / 256, 256>>>(u, Wgk, Wb, b_b, A_log, dt_bias);

    // conv + silu
    conv_silu_kernel<<<(cM * cKD + 255) / 256, 256>>>(qc, conv_q, cq, cKD);
    conv_silu_kernel<<<(cM * cKD + 255) / 256, 256>>>(kc, conv_k, ck, cKD);
    conv_silu_kernel<<<(cM * cVD + 255) / 256, 256>>>(vc, conv_v, cv, cVD);

    // reshape / normalize
    l2norm_qk_kernel<<<(2 * cM * cH * 32 + 255) / 256, 256>>>();
    reshape_v_kernel<<<(cM * cVD + 255) / 256, 256>>>();

    // delta-rule chunk precompute + scan
    chunk_pre_kernel<<<cBH * cNC, 256, CP_SMEM_FLOATS * sizeof(float)>>>();
    scan_kernel<<<dim3(6, cBH), 256, SC_SMEM_FLOATS * sizeof(float)>>>();

    // gated rms norm + output projection
    gate_norm_kernel<<<(cM * cH * 32 + 255) / 256, 256>>>(norm_w);
    sgemm_kernel<<<dim3(cD / 128, cM / 128), 256>>>(on, Wo, out, cM, cD, cVD);
}

// round 2
// speedup vs baseline: 1.0025x; 1.0025x over previous
#include <cuda_runtime.h>
#include <math.h>
#include <stdint.h>

// ---------------- problem constants ----------------
constexpr int cB  = 2;
constexpr int cL  = 4096;
constexpr int cD  = 1024;   // D_MODEL
constexpr int cKD = 768;    // KEY_DIM
constexpr int cVD = 1536;   // VALUE_DIM
constexpr int cH  = 8;
constexpr int cDK = 96;     // per-head qk dim
constexpr int cDV = 192;    // per-head v dim
constexpr int cCS = 64;     // chunk size
constexpr int cNC = cL / cCS;       // 64 chunks per sequence
constexpr int cM  = cB * cL;        // 8192 tokens
constexpr int cBH = cB * cH;        // 16

// ---------------- scratch (device globals; no cudaMalloc allowed) ----------------
__device__ float g_qc [cM * cKD];
__device__ float g_kc [cM * cKD];
__device__ float g_vc [cM * cVD];
__device__ float g_g  [cM * cVD];
__device__ float g_cq [cM * cKD];
__device__ float g_ck [cM * cKD];
__device__ float g_cv [cM * cVD];
__device__ float g_qn [cM * cKD];   // head layout; becomes qe after chunk_pre
__device__ float g_kn [cM * cKD];   // head layout; becomes kd after chunk_pre
__device__ float g_vh [cM * cVD];   // head layout; becomes u_ after chunk_pre
__device__ float g_kce[cM * cKD];   // kcd * exp(dec)
__device__ float g_gk [cBH * cL];
__device__ float g_bt [cBH * cL];
__device__ float g_at [cBH * cNC * cCS * cCS];  // intra-chunk attn
__device__ float g_edl[cBH * cNC];
__device__ float g_o  [cM * cVD];   // (b,h,l,dv)
__device__ float g_on [cM * cVD];   // (b,l,h*dv) gated+normed

// ---------------- generic SGEMM: C[M,N] = A[M,K] @ B[K,N], all row-major ----------------
// M%128==0, N%128==0, K%8==0 for all uses here.
__global__ void sgemm_kernel(const float* __restrict__ A, const float* __restrict__ B,
                             float* __restrict__ C, int M, int N, int K)
{
    __shared__ float As[8][128];
    __shared__ float Bs[8][128];
    const int tid = threadIdx.x;
    const int bm = blockIdx.y * 128;
    const int bn = blockIdx.x * 128;

    const int a_row = tid >> 1;          // 0..127
    const int a_col = (tid & 1) * 4;     // 0 or 4
    const int b_row = tid >> 5;          // 0..7
    const int b_col = (tid & 31) * 4;    // 0..124

    const int ty = tid >> 4;             // 0..15
    const int tx = tid & 15;             // 0..15

    float acc[8][8];
#pragma unroll
    for (int i = 0; i < 8; i++)
#pragma unroll
        for (int j = 0; j < 8; j++) acc[i][j] = 0.f;

    for (int k0 = 0; k0 < K; k0 += 8) {
        float4 av = *(const float4*)(A + (size_t)(bm + a_row) * K + k0 + a_col);
        As[a_col + 0][a_row] = av.x;
        As[a_col + 1][a_row] = av.y;
        As[a_col + 2][a_row] = av.z;
        As[a_col + 3][a_row] = av.w;
        float4 bv = *(const float4*)(B + (size_t)(k0 + b_row) * N + bn + b_col);
        *(float4*)&Bs[b_row][b_col] = bv;
        __syncthreads();
#pragma unroll
        for (int kk = 0; kk < 8; kk++) {
            float ra[8], rb[8];
#pragma unroll
            for (int i = 0; i < 8; i++) ra[i] = As[kk][ty * 8 + i];
#pragma unroll
            for (int j = 0; j < 8; j++) rb[j] = Bs[kk][tx * 8 + j];
#pragma unroll
            for (int i = 0; i < 8; i++)
#pragma unroll
                for (int j = 0; j < 8; j++) acc[i][j] += ra[i] * rb[j];
        }
        __syncthreads();
    }
#pragma unroll
    for (int i = 0; i < 8; i++) {
        float4* cp = (float4*)(C + (size_t)(bm + ty * 8 + i) * N + bn + tx * 8);
        cp[0] = make_float4(acc[i][0], acc[i][1], acc[i][2], acc[i][3]);
        cp[1] = make_float4(acc[i][4], acc[i][5], acc[i][6], acc[i][7]);
    }
}

// ---------------- gk / beta small projections + nonlinearity ----------------
__global__ void proj_gates_kernel(const float* __restrict__ u, const float* __restrict__ Wgk,
                                  const float* __restrict__ Wb, const float* __restrict__ b_b,
                                  const float* __restrict__ A_log, const float* __restrict__ dt_bias)
{
    int idx = blockIdx.x * blockDim.x + threadIdx.x;
    if (idx >= cM * cH) return;
    int m = idx / cH, h = idx % cH;
    const float* ur = u + (size_t)m * cD;
    float s1 = 0.f, s2 = 0.f;
    for (int i = 0; i < cD; i++) {
        float uv = ur[i];
        s1 += uv * Wgk[i * cH + h];
        s2 += uv * Wb [i * cH + h];
    }
    float x  = s1 + dt_bias[h];
    float sp = (x > 20.f) ? x : log1pf(expf(x));
    float gkv = -expf(A_log[h]) * sp;
    float bv  = 1.f / (1.f + expf(-(s2 + b_b[h])));
    int b = m / cL, l = m % cL;
    size_t o = ((size_t)(b * cH + h)) * cL + l;
    g_gk[o] = gkv;
    g_bt[o] = bv;
}

// ---------------- causal depthwise conv (K=4) + SiLU ----------------
__global__ void conv_silu_kernel(const float* __restrict__ x, const float* __restrict__ w,
                                 float* __restrict__ y, int C)
{
    int idx = blockIdx.x * blockDim.x + threadIdx.x;
    if (idx >= cM * C) return;
    int c = idx % C;
    int m = idx / C;
    int l = m % cL;
    float acc = 0.f;
#pragma unroll
    for (int j = 0; j < 4; j++) {
        int ll = l - 3 + j;
        if (ll >= 0) acc += x[(size_t)(m - l + ll) * C + c] * w[c * 4 + j];
    }
    y[idx] = acc / (1.f + expf(-acc));
}

// ---------------- L2 norm q,k + reshape to head layout ----------------
__global__ void l2norm_qk_kernel()
{
    int gw = (blockIdx.x * blockDim.x + threadIdx.x) >> 5;
    int lane = threadIdx.x & 31;
    if (gw >= 2 * cM * cH) return;
    int t = gw & 1;
    int rest = gw >> 1;
    int h = rest % cH;
    int m = rest / cH;
    const float* src = (t ? g_ck : g_cq) + (size_t)m * cKD + h * cDK;
    float v0 = src[lane], v1 = src[lane + 32], v2 = src[lane + 64];
    float ss = v0 * v0 + v1 * v1 + v2 * v2;
#pragma unroll
    for (int o = 16; o; o >>= 1) ss += __shfl_xor_sync(0xffffffffu, ss, o);
    float nrm = sqrtf(ss);
    float inv = 1.f / fmaxf(nrm, 1e-12f);
    int b = m / cL, l = m % cL;
    float* dst = (t ? g_kn : g_qn) + ((size_t)(b * cH + h) * cL + l) * cDK;
    dst[lane]      = v0 * inv;
    dst[lane + 32] = v1 * inv;
    dst[lane + 64] = v2 * inv;
}

// ---------------- v reshape to head layout ----------------
__global__ void reshape_v_kernel()
{
    int idx = blockIdx.x * blockDim.x + threadIdx.x;
    if (idx >= cM * cVD) return;
    int c = idx % cVD;
    int m = idx / cVD;
    int h = c / cDV, d = c % cDV;
    int b = m / cL, l = m % cL;
    g_vh[((size_t)(b * cH + h) * cL + l) * cDV + d] = g_cv[idx];
}

// ---------------- per-chunk precompute ----------------
// smem: sq(6144) sk(6144) skb(6144) sKK(4096) sM(4096) sv(12288) sdec(64) sbeta(64)
constexpr int CP_SMEM_FLOATS = 3 * 6144 + 4096 + 4096 + 12288 + 64 + 64;
__global__ void chunk_pre_kernel()
{
    extern __shared__ float sm[];
    float* sq   = sm;
    float* sk   = sq + 6144;
    float* skb  = sk + 6144;
    float* sKK  = skb + 6144;
    float* sM   = sKK + 4096;
    float* sv   = sM + 4096;
    float* sdec = sv + 12288;
    float* sbet = sdec + 64;

    const int tid = threadIdx.x;
    const int cid = blockIdx.x;           // 0..1023
    const int bh = cid / cNC;
    const int n  = cid % cNC;
    const size_t cbg  = (size_t)bh * cL + n * cCS;
    const size_t cb96  = cbg * cDK;
    const size_t cb192 = cbg * cDV;
    const float scale = rsqrtf((float)cDK);

    for (int i = tid; i < 6144; i += 256) { sq[i] = g_qn[cb96 + i]; sk[i] = g_kn[cb96 + i]; }
    if (tid < 64) sbet[tid] = g_bt[cbg + tid];
    __syncthreads();
    if (tid == 0) {
        float s = 0.f;
        for (int i = 0; i < 64; i++) { s += g_gk[cbg + i]; sdec[i] = s; }
    }
    __syncthreads();
    const float dl = sdec[63];

    for (int i = tid; i < 6144; i += 256)  skb[i] = sk[i] * sbet[i / cDK];
    for (int i = tid; i < 12288; i += 256) sv[i]  = g_vh[cb192 + i] * sbet[i / cDV];

    // write qe and kd back in place (shared copies keep originals)
    for (int i = tid; i < 6144; i += 256) {
        int c = i / cDK;
        g_qn[cb96 + i] = sq[i] * scale * expf(sdec[c]);
        g_kn[cb96 + i] = sk[i] * expf(dl - sdec[c]);
    }
    __syncthreads();

    // KK = kb @ k^T
    for (int idx = tid; idx < 4096; idx += 256) {
        int i = idx >> 6, j = idx & 63;
        float s = 0.f;
#pragma unroll 4
        for (int d = 0; d < cDK; d++) s += skb[i * cDK + d] * sk[j * cDK + d];
        sKK[idx] = s;
    }
    // intra-chunk attn (incl diagonal)
    for (int idx = tid; idx < 4096; idx += 256) {
        int i = idx >> 6, j = idx & 63;
        float a = 0.f;
        if (i >= j) {
            float s = 0.f;
#pragma unroll 4
            for (int d = 0; d < cDK; d++) s += sq[i * cDK + d] * sk[j * cDK + d];
            a = s * scale * expf(sdec[i] - sdec[j]);
        }
        g_at[(size_t)cid * 4096 + idx] = a;
    }
    // M1 = KK * Lmask, strict lower
    for (int idx = tid; idx < 4096; idx += 256) {
        int i = idx >> 6, j = idx & 63;
        sM[idx] = (i > j) ? sKK[idx] * expf(sdec[i] - sdec[j]) : 0.f;
    }
    __syncthreads();

    // forward substitution: u_ = M1^{-1} v   (in place in sv, 192 cols)
    for (int i = 1; i < 64; i++) {
        if (tid < 192) {
            float s = 0.f;
            for (int j = 0; j < i; j++) s += sM[i * 64 + j] * sv[j * 192 + tid];
            sv[i * 192 + tid] -= s;
        }
        __syncthreads();
    }
    // forward substitution: kcd = M2^{-1} kb  (M2 strict lower = KK; in place in skb, 96 cols)
    for (int i = 1; i < 64; i++) {
        if (tid < 96) {
            float s = 0.f;
            for (int j = 0; j < i; j++) s += sKK[i * 64 + j] * skb[j * 96 + tid];
            skb[i * 96 + tid] -= s;
        }
        __syncthreads();
    }

    for (int i = tid; i < 12288; i += 256) g_vh[cb192 + i] = sv[i];
    for (int i = tid; i < 6144; i += 256) {
        int c = i / cDK;
        g_kce[cb96 + i] = skb[i] * expf(sdec[c]);
    }
    if (tid == 0) g_edl[cid] = expf(dl);
}

// ---------------- sequential scan over chunks ----------------
// grid (6, 16): x = 32-wide value-column split, y = bh
constexpr int SC_SMEM_FLOATS = 3 * 6144 + 4096 + 2048 + 2048 + 3072;
__global__ void scan_kernel()
{
    extern __shared__ float sm[];
    float* sqe  = sm;
    float* skce = sqe + 6144;
    float* skd  = skce + 6144;
    float* sat  = skd + 6144;
    float* su   = sat + 4096;
    float* svn  = su + 2048;
    float* S    = svn + 2048;   // 96 x 32

    const int tid = threadIdx.x;
    const int bh = blockIdx.y;
    const int e0 = blockIdx.x * 32;
    const int e  = tid & 31;
    const int c0 = (tid >> 5) * 8;
    const int d0 = (tid >> 5) * 12;

    for (int i = tid; i < 3072; i += 256) S[i] = 0.f;

    for (int n = 0; n < cNC; n++) {
        const size_t cbg = (size_t)bh * cL + n * cCS;
        const size_t cb96 = cbg * cDK;
        const size_t cb192 = cbg * cDV;
        __syncthreads();
        for (int i = tid; i < 6144; i += 256) {
            sqe[i]  = g_qn[cb96 + i];
            skce[i] = g_kce[cb96 + i];
            skd[i]  = g_kn[cb96 + i];
        }
        for (int i = tid; i < 4096; i += 256)
            sat[i] = g_at[(size_t)(bh * cNC + n) * 4096 + i];
        for (int i = tid; i < 2048; i += 256) {
            int c = i >> 5, ee = i & 31;
            su[i] = g_vh[cb192 + (size_t)c * cDV + e0 + ee];
        }
        __syncthreads();

        // v_new = u - kce @ S
        float acc[8];
#pragma unroll
        for (int i = 0; i < 8; i++) acc[i] = 0.f;
        for (int j = 0; j < cDK; j++) {
            float sj = S[j * 32 + e];
#pragma unroll
            for (int i = 0; i < 8; i++) acc[i] += skce[(c0 + i) * cDK + j] * sj;
        }
#pragma unroll
        for (int i = 0; i < 8; i++) svn[(c0 + i) * 32 + e] = su[(c0 + i) * 32 + e] - acc[i];
        __syncthreads();

        // o = qe @ S + attn @ v_new
#pragma unroll
        for (int i = 0; i < 8; i++) acc[i] = 0.f;
        for (int j = 0; j < cDK; j++) {
            float sj = S[j * 32 + e];
#pragma unroll
            for (int i = 0; i < 8; i++) acc[i] += sqe[(c0 + i) * cDK + j] * sj;
        }
        for (int j = 0; j < 64; j++) {
            float vj = svn[j * 32 + e];
#pragma unroll
            for (int i = 0; i < 8; i++) acc[i] += sat[(c0 + i) * 64 + j] * vj;
        }
#pragma unroll
        for (int i = 0; i < 8; i++)
            g_o[cb192 + (size_t)(c0 + i) * cDV + e0 + e] = acc[i];
        __syncthreads();

        // S = S*exp(dl) + kd^T @ v_new
        const float el = g_edl[bh * cNC + n];
        float accS[12];
#pragma unroll
        for (int ii = 0; ii < 12; ii++) accS[ii] = 0.f;
        for (int c = 0; c < 64; c++) {
            float v = svn[c * 32 + e];
#pragma unroll
            for (int ii = 0; ii < 12; ii++) accS[ii] += skd[c * cDK + d0 + ii] * v;
        }
#pragma unroll
        for (int ii = 0; ii < 12; ii++) {
            int idx = (d0 + ii) * 32 + e;
            S[idx] = S[idx] * el + accS[ii];
        }
    }
}

// ---------------- gated RMS norm + transpose back ----------------
__global__ void gate_norm_kernel(const float* __restrict__ norm_w)
{
    int gw = (blockIdx.x * blockDim.x + threadIdx.x) >> 5;
    int lane = threadIdx.x & 31;
    if (gw >= cM * cH) return;
    int m = gw / cH, h = gw % cH;
    int b = m / cL, l = m % cL;
    const float* orow = g_o + ((size_t)(b * cH + h) * cL + l) * cDV;
    float vals[6];
    float ss = 0.f;
#pragma unroll
    for (int k = 0; k < 6; k++) {
        float v = orow[lane + 32 * k];
        vals[k] = v;
        ss += v * v;
    }
#pragma unroll
    for (int o = 16; o; o >>= 1) ss += __shfl_xor_sync(0xffffffffu, ss, o);
    float r = 1.f / sqrtf(ss / (float)cDV + 1e-5f);
#pragma unroll
    for (int k = 0; k < 6; k++) {
        int d = lane + 32 * k;
        size_t gi = (size_t)m * cVD + h * cDV + d;
        float gg = g_g[gi];
        float sg = gg / (1.f + expf(-gg));
        g_on[gi] = vals[k] * r * norm_w[d] * sg;
    }
}

// ---------------- host launch ----------------
static float* sym(const void* symbol)
{
    void* p = nullptr;
    cudaGetSymbolAddress(&p, symbol);
    return (float*)p;
}

extern "C" void kernel_launch(void* const* d_in, const int* in_sizes, int n_in,
                              void* d_out, int out_size)
{
    const float* u       = (const float*)d_in[0];
    const float* Wq      = (const float*)d_in[1];
    const float* Wk      = (const float*)d_in[2];
    const float* Wv      = (const float*)d_in[3];
    const float* Wg      = (const float*)d_in[4];
    const float* Wo      = (const float*)d_in[5];
    const float* Wgk     = (const float*)d_in[6];
    const float* Wb      = (const float*)d_in[7];
    const float* b_b     = (const float*)d_in[8];
    const float* A_log   = (const float*)d_in[9];
    const float* dt_bias = (const float*)d_in[10];
    const float* conv_q  = (const float*)d_in[11];
    const float* conv_k  = (const float*)d_in[12];
    const float* conv_v  = (const float*)d_in[13];
    const float* norm_w  = (const float*)d_in[14];
    float* out = (float*)d_out;

    float* qc = sym(g_qc); float* kc = sym(g_kc); float* vc = sym(g_vc); float* gg = sym(g_g);
    float* cq = sym(g_cq); float* ck = sym(g_ck); float* cv = sym(g_cv);
    float* on = sym(g_on);

    cudaFuncSetAttribute(chunk_pre_kernel, cudaFuncAttributeMaxDynamicSharedMemorySize,
                         CP_SMEM_FLOATS * (int)sizeof(float));
    cudaFuncSetAttribute(scan_kernel, cudaFuncAttributeMaxDynamicSharedMemorySize,
                         SC_SMEM_FLOATS * (int)sizeof(float));

    // projections
    sgemm_kernel<<<dim3(cKD / 128, cM / 128), 256>>>(u, Wq, qc, cM, cKD, cD);
    sgemm_kernel<<<dim3(cKD / 128, cM / 128), 256>>>(u, Wk, kc, cM, cKD, cD);
    sgemm_kernel<<<dim3(cVD / 128, cM / 128), 256>>>(u, Wv, vc, cM, cVD, cD);
    sgemm_kernel<<<dim3(cVD / 128, cM / 128), 256>>>(u, Wg, gg, cM, cVD, cD);
    proj_gates_kernel<<<(cM * cH + 255) / 256, 256>>>(u, Wgk, Wb, b_b, A_log, dt_bias);

    // conv + silu
    conv_silu_kernel<<<(cM * cKD + 255) / 256, 256>>>(qc, conv_q, cq, cKD);
    conv_silu_kernel<<<(cM * cKD + 255) / 256, 256>>>(kc, conv_k, ck, cKD);
    conv_silu_kernel<<<(cM * cVD + 255) / 256, 256>>>(vc, conv_v, cv, cVD);

    // reshape / normalize
    l2norm_qk_kernel<<<(2 * cM * cH * 32 + 255) / 256, 256>>>();
    reshape_v_kernel<<<(cM * cVD + 255) / 256, 256>>>();

    // delta-rule chunk precompute + scan
    chunk_pre_kernel<<<cBH * cNC, 256, CP_SMEM_FLOATS * sizeof(float)>>>();
    scan_kernel<<<dim3(6, cBH), 256, SC_SMEM_FLOATS * sizeof(float)>>>();

    // gated rms norm + output projection
    gate_norm_kernel<<<(cM * cH * 32 + 255) / 256, 256>>>(norm_w);
    sgemm_kernel<<<dim3(cD / 128, cM / 128), 256>>>(on, Wo, out, cM, cD, cVD);
}

// round 3
// speedup vs baseline: 1.0543x; 1.0516x over previous
#include <cuda_runtime.h>
#include <math.h>
#include <stdint.h>

// ---------------- problem constants ----------------
constexpr int cB  = 2;
constexpr int cL  = 4096;
constexpr int cD  = 1024;   // D_MODEL
constexpr int cKD = 768;    // KEY_DIM
constexpr int cVD = 1536;   // VALUE_DIM
constexpr int cH  = 8;
constexpr int cDK = 96;     // per-head qk dim
constexpr int cDV = 192;    // per-head v dim
constexpr int cCS = 64;     // chunk size
constexpr int cNC = cL / cCS;       // 64 chunks per sequence
constexpr int cM  = cB * cL;        // 8192 tokens
constexpr int cBH = cB * cH;        // 16
constexpr int cNP = cKD + cKD + cVD + cVD;  // 4608 packed projection width

// ---------------- scratch (device globals; no cudaMalloc allowed) ----------------
__device__ float g_Wcat[cD * cNP];      // packed [Wq|Wk|Wv|Wg]
__device__ float g_proj[cM * cNP];      // packed projection outputs
__device__ float g_cq [cM * cKD];
__device__ float g_ck [cM * cKD];
__device__ float g_cv [cM * cVD];
__device__ float g_qn [cM * cKD];   // head layout; becomes qe after chunk_pre
__device__ float g_kn [cM * cKD];   // head layout; becomes kd after chunk_pre
__device__ float g_vh [cM * cVD];   // head layout; becomes u_ after chunk_pre
__device__ float g_kce[cM * cKD];   // kcd * exp(dec)
__device__ float g_gk [cBH * cL];
__device__ float g_bt [cBH * cL];
__device__ float g_at [cBH * cNC * cCS * cCS];  // intra-chunk attn
__device__ float g_edl[cBH * cNC];
__device__ float g_o  [cM * cVD];   // (b,h,l,dv)
__device__ float g_on [cM * cVD];   // (b,l,h*dv) gated+normed

// ---------------- tf32 helpers ----------------
__device__ __forceinline__ uint32_t f2tf32(float f)
{
    uint32_t r;
    asm("cvt.rna.tf32.f32 %0, %1;" : "=r"(r) : "f"(f));
    return r;
}

__device__ __forceinline__ void mma_tf32(float c[4], const uint32_t a[4], const uint32_t b[2])
{
    asm volatile(
        "mma.sync.aligned.m16n8k8.row.col.f32.tf32.tf32.f32 "
        "{%0,%1,%2,%3}, {%4,%5,%6,%7}, {%8,%9}, {%0,%1,%2,%3};"
        : "+f"(c[0]), "+f"(c[1]), "+f"(c[2]), "+f"(c[3])
        : "r"(a[0]), "r"(a[1]), "r"(a[2]), "r"(a[3]), "r"(b[0]), "r"(b[1]));
}

// ---------------- tf32 tensor-core GEMM ----------------
// C[M,N] = A[M,K] @ B[K,N], row-major; M%128==0, N%128==0, K%16==0.
// 128x128x16 tile, 256 threads (2x4 warps, each 64x32), double-buffered smem.
__global__ void gemm_tf32_kernel(const float* __restrict__ A, int lda,
                                 const float* __restrict__ B, int ldb,
                                 float* __restrict__ C, int ldc,
                                 int M, int N, int K)
{
    __shared__ uint32_t As[2][128][20];   // [m][k], padded
    __shared__ uint32_t Bs[2][16][136];   // [k][n], padded

    const int tid  = threadIdx.x;
    const int wid  = tid >> 5;
    const int lane = tid & 31;
    const int g    = lane >> 2;
    const int t    = lane & 3;
    const int wm   = (wid >> 2) * 64;   // warp m offset
    const int wn   = (wid & 3) * 32;    // warp n offset

    const int bm = blockIdx.y * 128;
    const int bn = blockIdx.x * 128;

    // global load indexing
    const int arow = tid >> 1;
    const int akb  = (tid & 1) * 8;
    const int bkr  = tid >> 4;
    const int bnb  = (tid & 15) * 8;

    const float* Ag = A + (size_t)(bm + arow) * lda + akb;
    const float* Bg = B + (size_t)bkr * ldb + bn + bnb;

    float acc[4][4][4];
#pragma unroll
    for (int i = 0; i < 4; i++)
#pragma unroll
        for (int j = 0; j < 4; j++)
#pragma unroll
            for (int r = 0; r < 4; r++) acc[i][j][r] = 0.f;

    float4 pa0, pa1, pb0, pb1;
    const int nt = K >> 4;

    // preload tile 0
    pa0 = *(const float4*)(Ag);
    pa1 = *(const float4*)(Ag + 4);
    pb0 = *(const float4*)(Bg);
    pb1 = *(const float4*)(Bg + 4);
    {
        uint32_t* ap = &As[0][arow][akb];
        ap[0] = f2tf32(pa0.x); ap[1] = f2tf32(pa0.y); ap[2] = f2tf32(pa0.z); ap[3] = f2tf32(pa0.w);
        ap[4] = f2tf32(pa1.x); ap[5] = f2tf32(pa1.y); ap[6] = f2tf32(pa1.z); ap[7] = f2tf32(pa1.w);
        uint32_t* bp = &Bs[0][bkr][bnb];
        bp[0] = f2tf32(pb0.x); bp[1] = f2tf32(pb0.y); bp[2] = f2tf32(pb0.z); bp[3] = f2tf32(pb0.w);
        bp[4] = f2tf32(pb1.x); bp[5] = f2tf32(pb1.y); bp[6] = f2tf32(pb1.z); bp[7] = f2tf32(pb1.w);
    }
    __syncthreads();

    for (int kt = 0; kt < nt; kt++) {
        const int buf = kt & 1;
        if (kt + 1 < nt) {
            const float* Agn = Ag + (size_t)(kt + 1) * 16;
            const float* Bgn = Bg + (size_t)(kt + 1) * 16 * ldb;
            pa0 = *(const float4*)(Agn);
            pa1 = *(const float4*)(Agn + 4);
            pb0 = *(const float4*)(Bgn);
            pb1 = *(const float4*)(Bgn + 4);
        }
#pragma unroll
        for (int ks = 0; ks < 16; ks += 8) {
            uint32_t af[4][4], bf[4][2];
#pragma unroll
            for (int mi = 0; mi < 4; mi++) {
                int mr = wm + mi * 16;
                af[mi][0] = As[buf][mr + g][ks + t];
                af[mi][1] = As[buf][mr + g + 8][ks + t];
                af[mi][2] = As[buf][mr + g][ks + t + 4];
                af[mi][3] = As[buf][mr + g + 8][ks + t + 4];
            }
#pragma unroll
            for (int ni = 0; ni < 4; ni++) {
                int nc = wn + ni * 8;
                bf[ni][0] = Bs[buf][ks + t][nc + g];
                bf[ni][1] = Bs[buf][ks + t + 4][nc + g];
            }
#pragma unroll
            for (int mi = 0; mi < 4; mi++)
#pragma unroll
                for (int ni = 0; ni < 4; ni++)
                    mma_tf32(acc[mi][ni], af[mi], bf[ni]);
        }
        if (kt + 1 < nt) {
            uint32_t* ap = &As[buf ^ 1][arow][akb];
            ap[0] = f2tf32(pa0.x); ap[1] = f2tf32(pa0.y); ap[2] = f2tf32(pa0.z); ap[3] = f2tf32(pa0.w);
            ap[4] = f2tf32(pa1.x); ap[5] = f2tf32(pa1.y); ap[6] = f2tf32(pa1.z); ap[7] = f2tf32(pa1.w);
            uint32_t* bp = &Bs[buf ^ 1][bkr][bnb];
            bp[0] = f2tf32(pb0.x); bp[1] = f2tf32(pb0.y); bp[2] = f2tf32(pb0.z); bp[3] = f2tf32(pb0.w);
            bp[4] = f2tf32(pb1.x); bp[5] = f2tf32(pb1.y); bp[6] = f2tf32(pb1.z); bp[7] = f2tf32(pb1.w);
        }
        __syncthreads();
    }

    // epilogue
#pragma unroll
    for (int mi = 0; mi < 4; mi++) {
#pragma unroll
        for (int ni = 0; ni < 4; ni++) {
            int row0 = bm + wm + mi * 16 + g;
            int col  = bn + wn + ni * 8 + 2 * t;
            *(float2*)(C + (size_t)row0 * ldc + col) = make_float2(acc[mi][ni][0], acc[mi][ni][1]);
            *(float2*)(C + (size_t)(row0 + 8) * ldc + col) = make_float2(acc[mi][ni][2], acc[mi][ni][3]);
        }
    }
}

// ---------------- pack [Wq|Wk|Wv|Wg] into one row-major matrix ----------------
__global__ void pack_w_kernel(const float* __restrict__ Wq, const float* __restrict__ Wk,
                              const float* __restrict__ Wv, const float* __restrict__ Wg)
{
    int idx = blockIdx.x * blockDim.x + threadIdx.x;
    if (idx >= cD * cNP) return;
    int row = idx / cNP, col = idx % cNP;
    float v;
    if (col < cKD)            v = Wq[row * cKD + col];
    else if (col < 2 * cKD)   v = Wk[row * cKD + col - cKD];
    else if (col < 2 * cKD + cVD) v = Wv[row * cVD + col - 2 * cKD];
    else                      v = Wg[row * cVD + col - 2 * cKD - cVD];
    g_Wcat[idx] = v;
}

// ---------------- gk / beta small projections + nonlinearity ----------------
__global__ void proj_gates_kernel(const float* __restrict__ u, const float* __restrict__ Wgk,
                                  const float* __restrict__ Wb, const float* __restrict__ b_b,
                                  const float* __restrict__ A_log, const float* __restrict__ dt_bias)
{
    int idx = blockIdx.x * blockDim.x + threadIdx.x;
    if (idx >= cM * cH) return;
    int m = idx / cH, h = idx % cH;
    const float* ur = u + (size_t)m * cD;
    float s1 = 0.f, s2 = 0.f;
    for (int i = 0; i < cD; i++) {
        float uv = ur[i];
        s1 += uv * Wgk[i * cH + h];
        s2 += uv * Wb [i * cH + h];
    }
    float x  = s1 + dt_bias[h];
    float sp = (x > 20.f) ? x : log1pf(expf(x));
    float gkv = -expf(A_log[h]) * sp;
    float bv  = 1.f / (1.f + expf(-(s2 + b_b[h])));
    int b = m / cL, l = m % cL;
    size_t o = ((size_t)(b * cH + h)) * cL + l;
    g_gk[o] = gkv;
    g_bt[o] = bv;
}

// ---------------- causal depthwise conv (K=4) + SiLU ----------------
// reads x (row stride ldx), writes dense y (row stride C)
__global__ void conv_silu_kernel(const float* __restrict__ x, int ldx,
                                 const float* __restrict__ w,
                                 float* __restrict__ y, int C)
{
    int idx = blockIdx.x * blockDim.x + threadIdx.x;
    if (idx >= cM * C) return;
    int c = idx % C;
    int m = idx / C;
    int l = m % cL;
    float acc = 0.f;
#pragma unroll
    for (int j = 0; j < 4; j++) {
        int ll = l - 3 + j;
        if (ll >= 0) acc += x[(size_t)(m - l + ll) * ldx + c] * w[c * 4 + j];
    }
    y[idx] = acc / (1.f + expf(-acc));
}

// ---------------- L2 norm q,k + reshape to head layout ----------------
__global__ void l2norm_qk_kernel()
{
    int gw = (blockIdx.x * blockDim.x + threadIdx.x) >> 5;
    int lane = threadIdx.x & 31;
    if (gw >= 2 * cM * cH) return;
    int t = gw & 1;
    int rest = gw >> 1;
    int h = rest % cH;
    int m = rest / cH;
    const float* src = (t ? g_ck : g_cq) + (size_t)m * cKD + h * cDK;
    float v0 = src[lane], v1 = src[lane + 32], v2 = src[lane + 64];
    float ss = v0 * v0 + v1 * v1 + v2 * v2;
#pragma unroll
    for (int o = 16; o; o >>= 1) ss += __shfl_xor_sync(0xffffffffu, ss, o);
    float nrm = sqrtf(ss);
    float inv = 1.f / fmaxf(nrm, 1e-12f);
    int b = m / cL, l = m % cL;
    float* dst = (t ? g_kn : g_qn) + ((size_t)(b * cH + h) * cL + l) * cDK;
    dst[lane]      = v0 * inv;
    dst[lane + 32] = v1 * inv;
    dst[lane + 64] = v2 * inv;
}

// ---------------- v reshape to head layout ----------------
__global__ void reshape_v_kernel()
{
    int idx = blockIdx.x * blockDim.x + threadIdx.x;
    if (idx >= cM * cVD) return;
    int c = idx % cVD;
    int m = idx / cVD;
    int h = c / cDV, d = c % cDV;
    int b = m / cL, l = m % cL;
    g_vh[((size_t)(b * cH + h) * cL + l) * cDV + d] = g_cv[idx];
}

// ---------------- per-chunk precompute ----------------
// smem: sq(6144) sk(6144) skb(6144) sKK(4096) sM(4096) sv(12288) sdec(64) sbeta(64)
constexpr int CP_SMEM_FLOATS = 3 * 6144 + 4096 + 4096 + 12288 + 64 + 64;
constexpr int CP_THREADS = 320;
__global__ void chunk_pre_kernel()
{
    extern __shared__ float sm[];
    float* sq   = sm;
    float* sk   = sq + 6144;
    float* skb  = sk + 6144;
    float* sKK  = skb + 6144;
    float* sM   = sKK + 4096;
    float* sv   = sM + 4096;
    float* sdec = sv + 12288;
    float* sbet = sdec + 64;

    const int tid = threadIdx.x;
    const int cid = blockIdx.x;           // 0..1023
    const int bh = cid / cNC;
    const int n  = cid % cNC;
    const size_t cbg  = (size_t)bh * cL + n * cCS;
    const size_t cb96  = cbg * cDK;
    const size_t cb192 = cbg * cDV;
    const float scale = rsqrtf((float)cDK);

    for (int i = tid; i < 1536; i += CP_THREADS) {
        ((float4*)sq)[i] = ((const float4*)(g_qn + cb96))[i];
        ((float4*)sk)[i] = ((const float4*)(g_kn + cb96))[i];
    }
    if (tid < 64) sbet[tid] = g_bt[cbg + tid];
    __syncthreads();
    if (tid == 0) {
        float s = 0.f;
        for (int i = 0; i < 64; i++) { s += g_gk[cbg + i]; sdec[i] = s; }
    }
    __syncthreads();
    const float dl = sdec[63];

    for (int i = tid; i < 6144; i += CP_THREADS)  skb[i] = sk[i] * sbet[i / cDK];
    for (int i = tid; i < 12288; i += CP_THREADS) sv[i]  = g_vh[cb192 + i] * sbet[i / cDV];

    // write qe and kd back in place (shared copies keep originals)
    for (int i = tid; i < 6144; i += CP_THREADS) {
        int c = i / cDK;
        g_qn[cb96 + i] = sq[i] * scale * expf(sdec[c]);
        g_kn[cb96 + i] = sk[i] * expf(dl - sdec[c]);
    }
    __syncthreads();

    // KK = kb @ k^T
    for (int idx = tid; idx < 4096; idx += CP_THREADS) {
        int i = idx >> 6, j = idx & 63;
        float s = 0.f;
        const float4* a4 = (const float4*)(skb + i * cDK);
        const float4* b4 = (const float4*)(sk + j * cDK);
#pragma unroll 6
        for (int d = 0; d < cDK / 4; d++) {
            float4 a = a4[d], b = b4[d];
            s += a.x * b.x + a.y * b.y + a.z * b.z + a.w * b.w;
        }
        sKK[idx] = s;
    }
    // intra-chunk attn (incl diagonal)
    for (int idx = tid; idx < 4096; idx += CP_THREADS) {
        int i = idx >> 6, j = idx & 63;
        float a = 0.f;
        if (i >= j) {
            float s = 0.f;
            const float4* a4 = (const float4*)(sq + i * cDK);
            const float4* b4 = (const float4*)(sk + j * cDK);
#pragma unroll 6
            for (int d = 0; d < cDK / 4; d++) {
                float4 x = a4[d], y = b4[d];
                s += x.x * y.x + x.y * y.y + x.z * y.z + x.w * y.w;
            }
            a = s * scale * expf(sdec[i] - sdec[j]);
        }
        g_at[(size_t)cid * 4096 + idx] = a;
    }
    // M1 = KK * Lmask, strict lower
    for (int idx = tid; idx < 4096; idx += CP_THREADS) {
        int i = idx >> 6, j = idx & 63;
        sM[idx] = (i > j) ? sKK[idx] * expf(sdec[i] - sdec[j]) : 0.f;
    }
    __syncthreads();

    // concurrent forward substitutions:
    //   tid <192 : u_ = M1^{-1} v   (192 value columns, in place in sv)
    //   192..287 : kcd = M2^{-1} kb (96 key columns, in place in skb)
    for (int i = 1; i < 64; i++) {
        if (tid < 192) {
            float s = 0.f;
            const float* mrow = sM + i * 64;
            int j = 0;
            for (; j + 4 <= i; j += 4) {
                float4 m4 = *(const float4*)(mrow + j);
                s += m4.x * sv[(j + 0) * 192 + tid] + m4.y * sv[(j + 1) * 192 + tid]
                   + m4.z * sv[(j + 2) * 192 + tid] + m4.w * sv[(j + 3) * 192 + tid];
            }
            for (; j < i; j++) s += mrow[j] * sv[j * 192 + tid];
            sv[i * 192 + tid] -= s;
        } else if (tid < 288) {
            int c = tid - 192;
            float s = 0.f;
            const float* krow = sKK + i * 64;
            int j = 0;
            for (; j + 4 <= i; j += 4) {
                float4 m4 = *(const float4*)(krow + j);
                s += m4.x * skb[(j + 0) * 96 + c] + m4.y * skb[(j + 1) * 96 + c]
                   + m4.z * skb[(j + 2) * 96 + c] + m4.w * skb[(j + 3) * 96 + c];
            }
            for (; j < i; j++) s += krow[j] * skb[j * 96 + c];
            skb[i * 96 + c] -= s;
        }
        __syncthreads();
    }

    for (int i = tid; i < 12288; i += CP_THREADS) g_vh[cb192 + i] = sv[i];
    for (int i = tid; i < 6144; i += CP_THREADS) {
        int c = i / cDK;
        g_kce[cb96 + i] = skb[i] * expf(sdec[c]);
    }
    if (tid == 0) g_edl[cid] = expf(dl);
}

// ---------------- sequential scan over chunks ----------------
// grid (6, 16): x = 32-wide value-column split, y = bh
constexpr int SC_SMEM_FLOATS = 3 * 6144 + 4096 + 2048 + 2048 + 3072;
__global__ void scan_kernel()
{
    extern __shared__ float sm[];
    float* sqe  = sm;
    float* skce = sqe + 6144;
    float* skd  = skce + 6144;
    float* sat  = skd + 6144;
    float* su   = sat + 4096;
    float* svn  = su + 2048;
    float* S    = svn + 2048;   // 96 x 32

    const int tid = threadIdx.x;
    const int bh = blockIdx.y;
    const int e0 = blockIdx.x * 32;
    const int e  = tid & 31;
    const int c0 = (tid >> 5) * 8;
    const int d0 = (tid >> 5) * 12;

    for (int i = tid; i < 3072; i += 256) S[i] = 0.f;

    for (int n = 0; n < cNC; n++) {
        const size_t cbg = (size_t)bh * cL + n * cCS;
        const size_t cb96 = cbg * cDK;
        const size_t cb192 = cbg * cDV;
        __syncthreads();
        for (int i = tid; i < 1536; i += 256) {
            ((float4*)sqe)[i]  = ((const float4*)(g_qn + cb96))[i];
            ((float4*)skce)[i] = ((const float4*)(g_kce + cb96))[i];
            ((float4*)skd)[i]  = ((const float4*)(g_kn + cb96))[i];
        }
        for (int i = tid; i < 1024; i += 256)
            ((float4*)sat)[i] = ((const float4*)(g_at + (size_t)(bh * cNC + n) * 4096))[i];
        for (int i = tid; i < 512; i += 256) {
            int c = i >> 3, ee = (i & 7) * 4;
            *(float4*)&su[c * 32 + ee] =
                *(const float4*)&g_vh[cb192 + (size_t)c * cDV + e0 + ee];
        }
        __syncthreads();

        // v_new = u - kce @ S
        float acc[8];
#pragma unroll
        for (int i = 0; i < 8; i++) acc[i] = 0.f;
        for (int j = 0; j < cDK; j += 4) {
            float s0 = S[(j + 0) * 32 + e];
            float s1 = S[(j + 1) * 32 + e];
            float s2 = S[(j + 2) * 32 + e];
            float s3 = S[(j + 3) * 32 + e];
#pragma unroll
            for (int i = 0; i < 8; i++) {
                float4 kv = *(const float4*)&skce[(c0 + i) * cDK + j];
                acc[i] += kv.x * s0 + kv.y * s1 + kv.z * s2 + kv.w * s3;
            }
        }
#pragma unroll
        for (int i = 0; i < 8; i++) svn[(c0 + i) * 32 + e] = su[(c0 + i) * 32 + e] - acc[i];
        __syncthreads();

        // o = qe @ S + attn @ v_new
#pragma unroll
        for (int i = 0; i < 8; i++) acc[i] = 0.f;
        for (int j = 0; j < cDK; j += 4) {
            float s0 = S[(j + 0) * 32 + e];
            float s1 = S[(j + 1) * 32 + e];
            float s2 = S[(j + 2) * 32 + e];
            float s3 = S[(j + 3) * 32 + e];
#pragma unroll
            for (int i = 0; i < 8; i++) {
                float4 qv = *(const float4*)&sqe[(c0 + i) * cDK + j];
                acc[i] += qv.x * s0 + qv.y * s1 + qv.z * s2 + qv.w * s3;
            }
        }
        for (int j = 0; j < 64; j += 4) {
            float v0 = svn[(j + 0) * 32 + e];
            float v1 = svn[(j + 1) * 32 + e];
            float v2 = svn[(j + 2) * 32 + e];
            float v3 = svn[(j + 3) * 32 + e];
#pragma unroll
            for (int i = 0; i < 8; i++) {
                float4 av = *(const float4*)&sat[(c0 + i) * 64 + j];
                acc[i] += av.x * v0 + av.y * v1 + av.z * v2 + av.w * v3;
            }
        }
#pragma unroll
        for (int i = 0; i < 8; i++)
            g_o[cb192 + (size_t)(c0 + i) * cDV + e0 + e] = acc[i];
        __syncthreads();

        // S = S*exp(dl) + kd^T @ v_new
        const float el = g_edl[bh * cNC + n];
        float accS[12];
#pragma unroll
        for (int ii = 0; ii < 12; ii++) accS[ii] = 0.f;
        for (int c = 0; c < 64; c++) {
            float v = svn[c * 32 + e];
            const float* kr = skd + c * cDK + d0;
            float4 k0 = *(const float4*)(kr);
            float4 k1 = *(const float4*)(kr + 4);
            float4 k2 = *(const float4*)(kr + 8);
            accS[0] += k0.x * v; accS[1] += k0.y * v; accS[2]  += k0.z * v; accS[3]  += k0.w * v;
            accS[4] += k1.x * v; accS[5] += k1.y * v; accS[6]  += k1.z * v; accS[7]  += k1.w * v;
            accS[8] += k2.x * v; accS[9] += k2.y * v; accS[10] += k2.z * v; accS[11] += k2.w * v;
        }
#pragma unroll
        for (int ii = 0; ii < 12; ii++) {
            int idx = (d0 + ii) * 32 + e;
            S[idx] = S[idx] * el + accS[ii];
        }
    }
}

// ---------------- gated RMS norm + transpose back ----------------
__global__ void gate_norm_kernel(const float* __restrict__ norm_w)
{
    int gw = (blockIdx.x * blockDim.x + threadIdx.x) >> 5;
    int lane = threadIdx.x & 31;
    if (gw >= cM * cH) return;
    int m = gw / cH, h = gw % cH;
    int b = m / cL, l = m % cL;
    const float* orow = g_o + ((size_t)(b * cH + h) * cL + l) * cDV;
    float vals[6];
    float ss = 0.f;
#pragma unroll
    for (int k = 0; k < 6; k++) {
        float v = orow[lane + 32 * k];
        vals[k] = v;
        ss += v * v;
    }
#pragma unroll
    for (int o = 16; o; o >>= 1) ss += __shfl_xor_sync(0xffffffffu, ss, o);
    float r = 1.f / sqrtf(ss / (float)cDV + 1e-5f);
#pragma unroll
    for (int k = 0; k < 6; k++) {
        int d = lane + 32 * k;
        float gg = g_proj[(size_t)m * cNP + 2 * cKD + cVD + h * cDV + d];
        float sg = gg / (1.f + expf(-gg));
        g_on[(size_t)m * cVD + h * cDV + d] = vals[k] * r * norm_w[d] * sg;
    }
}

// ---------------- host launch ----------------
static float* sym(const void* symbol)
{
    void* p = nullptr;
    cudaGetSymbolAddress(&p, symbol);
    return (float*)p;
}

extern "C" void kernel_launch(void* const* d_in, const int* in_sizes, int n_in,
                              void* d_out, int out_size)
{
    const float* u       = (const float*)d_in[0];
    const float* Wq      = (const float*)d_in[1];
    const float* Wk      = (const float*)d_in[2];
    const float* Wv      = (const float*)d_in[3];
    const float* Wg      = (const float*)d_in[4];
    const float* Wo      = (const float*)d_in[5];
    const float* Wgk     = (const float*)d_in[6];
    const float* Wb      = (const float*)d_in[7];
    const float* b_b     = (const float*)d_in[8];
    const float* A_log   = (const float*)d_in[9];
    const float* dt_bias = (const float*)d_in[10];
    const float* conv_q  = (const float*)d_in[11];
    const float* conv_k  = (const float*)d_in[12];
    const float* conv_v  = (const float*)d_in[13];
    const float* norm_w  = (const float*)d_in[14];
    float* out = (float*)d_out;

    float* Wcat = sym(g_Wcat);
    float* proj = sym(g_proj);
    float* cq = sym(g_cq); float* ck = sym(g_ck); float* cv = sym(g_cv);
    float* on = sym(g_on);

    cudaFuncSetAttribute(chunk_pre_kernel, cudaFuncAttributeMaxDynamicSharedMemorySize,
                         CP_SMEM_FLOATS * (int)sizeof(float));
    cudaFuncSetAttribute(scan_kernel, cudaFuncAttributeMaxDynamicSharedMemorySize,
                         SC_SMEM_FLOATS * (int)sizeof(float));

    // pack weights + fused projection GEMM (q|k|v|g)
    pack_w_kernel<<<(cD * cNP + 255) / 256, 256>>>(Wq, Wk, Wv, Wg);
    gemm_tf32_kernel<<<dim3(cNP / 128, cM / 128), 256>>>(u, cD, Wcat, cNP, proj, cNP, cM, cNP, cD);
    proj_gates_kernel<<<(cM * cH + 255) / 256, 256>>>(u, Wgk, Wb, b_b, A_log, dt_bias);

    // conv + silu (read from packed projection buffer)
    conv_silu_kernel<<<(cM * cKD + 255) / 256, 256>>>(proj,            cNP, conv_q, cq, cKD);
    conv_silu_kernel<<<(cM * cKD + 255) / 256, 256>>>(proj + cKD,      cNP, conv_k, ck, cKD);
    conv_silu_kernel<<<(cM * cVD + 255) / 256, 256>>>(proj + 2 * cKD,  cNP, conv_v, cv, cVD);

    // reshape / normalize
    l2norm_qk_kernel<<<(2 * cM * cH * 32 + 255) / 256, 256>>>();
    reshape_v_kernel<<<(cM * cVD + 255) / 256, 256>>>();

    // delta-rule chunk precompute + scan
    chunk_pre_kernel<<<cBH * cNC, CP_THREADS, CP_SMEM_FLOATS * sizeof(float)>>>();
    scan_kernel<<<dim3(6, cBH), 256, SC_SMEM_FLOATS * sizeof(float)>>>();

    // gated rms norm + output projection
    gate_norm_kernel<<<(cM * cH * 32 + 255) / 256, 256>>>(norm_w);
    gemm_tf32_kernel<<<dim3(cD / 128, cM / 128), 256>>>(on, cVD, Wo, cD, out, cD, cM, cD, cVD);
}

// round 4
// speedup vs baseline: 1.7978x; 1.7053x over previous
#include <cuda_runtime.h>
#include <math.h>
#include <stdint.h>

// ---------------- problem constants ----------------
constexpr int cB  = 2;
constexpr int cL  = 4096;
constexpr int cD  = 1024;   // D_MODEL
constexpr int cKD = 768;    // KEY_DIM
constexpr int cVD = 1536;   // VALUE_DIM
constexpr int cH  = 8;
constexpr int cDK = 96;     // per-head qk dim
constexpr int cDV = 192;    // per-head v dim
constexpr int cCS = 64;     // chunk size
constexpr int cNC = cL / cCS;       // 64 chunks per sequence
constexpr int cM  = cB * cL;        // 8192 tokens
constexpr int cBH = cB * cH;        // 16
constexpr int cNP = cKD + cKD + cVD + cVD;  // 4608 packed projection width

// ---------------- scratch (device globals; no cudaMalloc allowed) ----------------
__device__ uint32_t g_Wcat[cD * cNP];   // packed [Wq|Wk|Wv|Wg], tf32 bits
__device__ uint32_t g_WoT [cVD * cD];   // Wo, tf32 bits
__device__ uint32_t g_uT  [cM * cD];    // u, tf32 bits
__device__ float g_proj[cM * cNP];      // packed projection outputs (fp32)
__device__ float g_cq [cM * cKD];
__device__ float g_ck [cM * cKD];
__device__ float g_cv [cM * cVD];
__device__ float g_qn [cM * cKD];   // head layout; becomes qe after chunk_pre
__device__ float g_kn [cM * cKD];   // head layout; becomes kd after chunk_pre
__device__ float g_vh [cM * cVD];   // head layout; becomes u_ after chunk_pre
__device__ float g_kce[cM * cKD];   // kcd * exp(dec)
__device__ float g_gk [cBH * cL];
__device__ float g_bt [cBH * cL];
__device__ float g_at [cBH * cNC * cCS * cCS];  // intra-chunk attn
__device__ float g_edl[cBH * cNC];
__device__ float g_o  [cM * cVD];   // (b,h,l,dv)
__device__ uint32_t g_on [cM * cVD];   // gated+normed, tf32 bits

// ---------------- tf32 helpers ----------------
__device__ __forceinline__ uint32_t f2tf32(float f)
{
    uint32_t r;
    asm("cvt.rna.tf32.f32 %0, %1;" : "=r"(r) : "f"(f));
    return r;
}

__device__ __forceinline__ void mma_tf32(float c[4], const uint32_t a[4], const uint32_t b[2])
{
    asm volatile(
        "mma.sync.aligned.m16n8k8.row.col.f32.tf32.tf32.f32 "
        "{%0,%1,%2,%3}, {%4,%5,%6,%7}, {%8,%9}, {%0,%1,%2,%3};"
        : "+f"(c[0]), "+f"(c[1]), "+f"(c[2]), "+f"(c[3])
        : "r"(a[0]), "r"(a[1]), "r"(a[2]), "r"(a[3]), "r"(b[0]), "r"(b[1]));
}

#define CP16(dst, src) \
    asm volatile("cp.async.cg.shared.global [%0], [%1], 16;" :: "r"(dst), "l"(src))

// ---------------- tf32 tensor-core GEMM (cp.async double-buffered) ----------------
// C[M,N] = A[M,K] @ B[K,N], A/B already tf32 bit-patterns, row-major.
// M%128==0, N%128==0, K%16==0, K/16 >= 2.
__global__ void gemm_tf32_kernel(const uint32_t* __restrict__ A, int lda,
                                 const uint32_t* __restrict__ B, int ldb,
                                 float* __restrict__ C, int ldc,
                                 int M, int N, int K)
{
    __shared__ uint32_t As[2][128][20];   // [m][k], stride 20 -> conflict-free frag loads
    __shared__ uint32_t Bs[2][16][136];   // [k][n], stride 136 -> conflict-free frag loads

    const int tid  = threadIdx.x;
    const int wid  = tid >> 5;
    const int lane = tid & 31;
    const int g    = lane >> 2;
    const int t    = lane & 3;
    const int wm   = (wid >> 2) * 64;   // warp m offset
    const int wn   = (wid & 3) * 32;    // warp n offset

    const int bm = blockIdx.y * 128;
    const int bn = blockIdx.x * 128;

    const int arow = tid >> 1;           // 0..127
    const int akb  = (tid & 1) * 8;      // 0 or 8
    const int bkr  = tid >> 4;           // 0..15
    const int bnb  = (tid & 15) * 8;     // 0..120

    const uint32_t* Ag = A + (size_t)(bm + arow) * lda + akb;
    const uint32_t* Bg = B + (size_t)bkr * ldb + bn + bnb;

    const uint32_t sa0 = (uint32_t)__cvta_generic_to_shared(&As[0][arow][akb]);
    const uint32_t sa1 = (uint32_t)__cvta_generic_to_shared(&As[1][arow][akb]);
    const uint32_t sb0 = (uint32_t)__cvta_generic_to_shared(&Bs[0][bkr][bnb]);
    const uint32_t sb1 = (uint32_t)__cvta_generic_to_shared(&Bs[1][bkr][bnb]);

    float acc[4][4][4];
#pragma unroll
    for (int i = 0; i < 4; i++)
#pragma unroll
        for (int j = 0; j < 4; j++)
#pragma unroll
            for (int r = 0; r < 4; r++) acc[i][j][r] = 0.f;

    const int nt = K >> 4;

    // prologue: stage 0 and 1
    {
        const uint32_t* a = Ag;
        const uint32_t* b = Bg;
        CP16(sa0, a); CP16(sa0 + 16, a + 4);
        CP16(sb0, b); CP16(sb0 + 16, b + 4);
        asm volatile("cp.async.commit_group;");
        a = Ag + 16;
        b = Bg + (size_t)16 * ldb;
        CP16(sa1, a); CP16(sa1 + 16, a + 4);
        CP16(sb1, b); CP16(sb1 + 16, b + 4);
        asm volatile("cp.async.commit_group;");
    }

    for (int kt = 0; kt < nt; kt++) {
        if (kt == nt - 1) asm volatile("cp.async.wait_group 0;");
        else              asm volatile("cp.async.wait_group 1;");
        __syncthreads();

        const int buf = kt & 1;
#pragma unroll
        for (int ks = 0; ks < 16; ks += 8) {
            uint32_t af[4][4], bf[4][2];
#pragma unroll
            for (int mi = 0; mi < 4; mi++) {
                int mr = wm + mi * 16;
                af[mi][0] = As[buf][mr + g][ks + t];
                af[mi][1] = As[buf][mr + g + 8][ks + t];
                af[mi][2] = As[buf][mr + g][ks + t + 4];
                af[mi][3] = As[buf][mr + g + 8][ks + t + 4];
            }
#pragma unroll
            for (int ni = 0; ni < 4; ni++) {
                int nc = wn + ni * 8;
                bf[ni][0] = Bs[buf][ks + t][nc + g];
                bf[ni][1] = Bs[buf][ks + t + 4][nc + g];
            }
#pragma unroll
            for (int mi = 0; mi < 4; mi++)
#pragma unroll
                for (int ni = 0; ni < 4; ni++)
                    mma_tf32(acc[mi][ni], af[mi], bf[ni]);
        }
        __syncthreads();

        if (kt + 2 < nt) {
            const uint32_t* a = Ag + (size_t)(kt + 2) * 16;
            const uint32_t* b = Bg + (size_t)(kt + 2) * 16 * ldb;
            const uint32_t da = buf ? sa1 : sa0;
            const uint32_t db = buf ? sb1 : sb0;
            CP16(da, a); CP16(da + 16, a + 4);
            CP16(db, b); CP16(db + 16, b + 4);
            asm volatile("cp.async.commit_group;");
        }
    }

    // epilogue
#pragma unroll
    for (int mi = 0; mi < 4; mi++) {
#pragma unroll
        for (int ni = 0; ni < 4; ni++) {
            int row0 = bm + wm + mi * 16 + g;
            int col  = bn + wn + ni * 8 + 2 * t;
            *(float2*)(C + (size_t)row0 * ldc + col) = make_float2(acc[mi][ni][0], acc[mi][ni][1]);
            *(float2*)(C + (size_t)(row0 + 8) * ldc + col) = make_float2(acc[mi][ni][2], acc[mi][ni][3]);
        }
    }
}

// ---------------- pack [Wq|Wk|Wv|Wg] into one tf32 matrix ----------------
__global__ void pack_w_kernel(const float* __restrict__ Wq, const float* __restrict__ Wk,
                              const float* __restrict__ Wv, const float* __restrict__ Wg)
{
    int idx = blockIdx.x * blockDim.x + threadIdx.x;
    if (idx >= cD * cNP) return;
    int row = idx / cNP, col = idx % cNP;
    float v;
    if (col < cKD)            v = Wq[row * cKD + col];
    else if (col < 2 * cKD)   v = Wk[row * cKD + col - cKD];
    else if (col < 2 * cKD + cVD) v = Wv[row * cVD + col - 2 * cKD];
    else                      v = Wg[row * cVD + col - 2 * cKD - cVD];
    g_Wcat[idx] = f2tf32(v);
}

__global__ void pack_wo_kernel(const float* __restrict__ Wo)
{
    int idx = blockIdx.x * blockDim.x + threadIdx.x;
    if (idx >= cVD * cD) return;
    g_WoT[idx] = f2tf32(Wo[idx]);
}

__global__ void convert_u_kernel(const float* __restrict__ u, int off, int cnt)
{
    int idx = blockIdx.x * blockDim.x + threadIdx.x;
    if (idx >= cnt) return;
    g_uT[off + idx] = f2tf32(u[off + idx]);
}

// ---------------- gk / beta projections: warp per token, W in smem ----------------
// smem: 1024 rows x 16 floats (Wgk row | Wb row interleaved) = 64KB
__global__ void proj_gates_kernel(const float* __restrict__ u, const float* __restrict__ Wgk,
                                  const float* __restrict__ Wb, const float* __restrict__ b_b,
                                  const float* __restrict__ A_log, const float* __restrict__ dt_bias)
{
    extern __shared__ float sW[];   // [1024][16]
    const int tid = threadIdx.x;
    const int wid = tid >> 5;
    const int lane = tid & 31;

    for (int idx = tid; idx < cD * 16; idx += 256) {
        int i = idx >> 4, c = idx & 15;
        sW[idx] = (c < 8) ? Wgk[i * cH + c] : Wb[i * cH + (c - 8)];
    }
    __syncthreads();

    int m = blockIdx.x * 8 + wid;
    const float* ur = u + (size_t)m * cD;
    float s[16];
#pragma unroll
    for (int c = 0; c < 16; c++) s[c] = 0.f;
    for (int j = 0; j < 32; j++) {
        int i = lane + 32 * j;
        float uv = __ldg(ur + i);
        const float* wr = sW + i * 16;
#pragma unroll
        for (int c = 0; c < 16; c++) s[c] += uv * wr[c];
    }
#pragma unroll
    for (int c = 0; c < 16; c++) {
#pragma unroll
        for (int o = 16; o; o >>= 1) s[c] += __shfl_xor_sync(0xffffffffu, s[c], o);
    }
    if (lane < 8) {
        int h = lane;
        float x  = s[h] + dt_bias[h];
        float sp = (x > 20.f) ? x : log1pf(expf(x));
        float gkv = -expf(A_log[h]) * sp;
        int b = m / cL, l = m % cL;
        g_gk[((size_t)(b * cH + h)) * cL + l] = gkv;
    } else {
        int h = lane - 8;
        float bv = 1.f / (1.f + expf(-(s[8 + h] + b_b[h])));
        int b = m / cL, l = m % cL;
        g_bt[((size_t)(b * cH + h)) * cL + l] = bv;
    }
}

// ---------------- fused causal depthwise conv (K=4) + SiLU for q,k,v ----------------
__global__ void conv_silu_kernel(const float* __restrict__ wq, const float* __restrict__ wk,
                                 const float* __restrict__ wv)
{
    int idx = blockIdx.x * blockDim.x + threadIdx.x;
    if (idx >= cM * 3072) return;
    int c = idx % 3072;           // also the proj column (q|k|v occupy [0,3072))
    int m = idx / 3072;
    int l = m % cL;

    const float* w;
    float* y;
    if (c < cKD)            { w = wq + c * 4;            y = g_cq + (size_t)m * cKD + c; }
    else if (c < 2 * cKD)   { w = wk + (c - cKD) * 4;    y = g_ck + (size_t)m * cKD + (c - cKD); }
    else                    { w = wv + (c - 2 * cKD) * 4; y = g_cv + (size_t)m * cVD + (c - 2 * cKD); }

    float acc = 0.f;
#pragma unroll
    for (int j = 0; j < 4; j++) {
        int ll = l - 3 + j;
        if (ll >= 0) acc += g_proj[(size_t)(m - l + ll) * cNP + c] * w[j];
    }
    *y = acc / (1.f + expf(-acc));
}

// ---------------- L2 norm q,k + reshape to head layout ----------------
__global__ void l2norm_qk_kernel()
{
    int gw = (blockIdx.x * blockDim.x + threadIdx.x) >> 5;
    int lane = threadIdx.x & 31;
    if (gw >= 2 * cM * cH) return;
    int t = gw & 1;
    int rest = gw >> 1;
    int h = rest % cH;
    int m = rest / cH;
    const float* src = (t ? g_ck : g_cq) + (size_t)m * cKD + h * cDK;
    float v0 = src[lane], v1 = src[lane + 32], v2 = src[lane + 64];
    float ss = v0 * v0 + v1 * v1 + v2 * v2;
#pragma unroll
    for (int o = 16; o; o >>= 1) ss += __shfl_xor_sync(0xffffffffu, ss, o);
    float nrm = sqrtf(ss);
    float inv = 1.f / fmaxf(nrm, 1e-12f);
    int b = m / cL, l = m % cL;
    float* dst = (t ? g_kn : g_qn) + ((size_t)(b * cH + h) * cL + l) * cDK;
    dst[lane]      = v0 * inv;
    dst[lane + 32] = v1 * inv;
    dst[lane + 64] = v2 * inv;
}

// ---------------- v reshape to head layout ----------------
__global__ void reshape_v_kernel()
{
    int idx = blockIdx.x * blockDim.x + threadIdx.x;
    if (idx >= cM * cVD) return;
    int c = idx % cVD;
    int m = idx / cVD;
    int h = c / cDV, d = c % cDV;
    int b = m / cL, l = m % cL;
    g_vh[((size_t)(b * cH + h) * cL + l) * cDV + d] = g_cv[idx];
}

// ---------------- per-chunk precompute ----------------
constexpr int CP_SMEM_FLOATS = 3 * 6144 + 4096 + 4096 + 12288 + 64 + 64;
constexpr int CP_THREADS = 320;
__global__ void chunk_pre_kernel()
{
    extern __shared__ float sm[];
    float* sq   = sm;
    float* sk   = sq + 6144;
    float* skb  = sk + 6144;
    float* sKK  = skb + 6144;
    float* sM   = sKK + 4096;
    float* sv   = sM + 4096;
    float* sdec = sv + 12288;
    float* sbet = sdec + 64;

    const int tid = threadIdx.x;
    const int cid = blockIdx.x;           // 0..1023
    const int bh = cid / cNC;
    const int n  = cid % cNC;
    const size_t cbg  = (size_t)bh * cL + n * cCS;
    const size_t cb96  = cbg * cDK;
    const size_t cb192 = cbg * cDV;
    const float scale = rsqrtf((float)cDK);

    for (int i = tid; i < 1536; i += CP_THREADS) {
        ((float4*)sq)[i] = ((const float4*)(g_qn + cb96))[i];
        ((float4*)sk)[i] = ((const float4*)(g_kn + cb96))[i];
    }
    if (tid < 64) sbet[tid] = g_bt[cbg + tid];
    __syncthreads();
    if (tid == 0) {
        float s = 0.f;
        for (int i = 0; i < 64; i++) { s += g_gk[cbg + i]; sdec[i] = s; }
    }
    __syncthreads();
    const float dl = sdec[63];

    for (int i = tid; i < 6144; i += CP_THREADS)  skb[i] = sk[i] * sbet[i / cDK];
    for (int i = tid; i < 12288; i += CP_THREADS) sv[i]  = g_vh[cb192 + i] * sbet[i / cDV];

    // write qe and kd back in place (shared copies keep originals)
    for (int i = tid; i < 6144; i += CP_THREADS) {
        int c = i / cDK;
        g_qn[cb96 + i] = sq[i] * scale * expf(sdec[c]);
        g_kn[cb96 + i] = sk[i] * expf(dl - sdec[c]);
    }
    __syncthreads();

    // KK = kb @ k^T
    for (int idx = tid; idx < 4096; idx += CP_THREADS) {
        int i = idx >> 6, j = idx & 63;
        float s = 0.f;
        const float4* a4 = (const float4*)(skb + i * cDK);
        const float4* b4 = (const float4*)(sk + j * cDK);
#pragma unroll 6
        for (int d = 0; d < cDK / 4; d++) {
            float4 a = a4[d], b = b4[d];
            s += a.x * b.x + a.y * b.y + a.z * b.z + a.w * b.w;
        }
        sKK[idx] = s;
    }
    // intra-chunk attn (incl diagonal)
    for (int idx = tid; idx < 4096; idx += CP_THREADS) {
        int i = idx >> 6, j = idx & 63;
        float a = 0.f;
        if (i >= j) {
            float s = 0.f;
            const float4* a4 = (const float4*)(sq + i * cDK);
            const float4* b4 = (const float4*)(sk + j * cDK);
#pragma unroll 6
            for (int d = 0; d < cDK / 4; d++) {
                float4 x = a4[d], y = b4[d];
                s += x.x * y.x + x.y * y.y + x.z * y.z + x.w * y.w;
            }
            a = s * scale * expf(sdec[i] - sdec[j]);
        }
        g_at[(size_t)cid * 4096 + idx] = a;
    }
    // M1 = KK * Lmask, strict lower
    for (int idx = tid; idx < 4096; idx += CP_THREADS) {
        int i = idx >> 6, j = idx & 63;
        sM[idx] = (i > j) ? sKK[idx] * expf(sdec[i] - sdec[j]) : 0.f;
    }
    __syncthreads();

    // concurrent forward substitutions:
    //   tid <192 : u_ = M1^{-1} v   (192 value columns, in place in sv)
    //   192..287 : kcd = M2^{-1} kb (96 key columns, in place in skb)
    for (int i = 1; i < 64; i++) {
        if (tid < 192) {
            float s = 0.f;
            const float* mrow = sM + i * 64;
            int j = 0;
            for (; j + 4 <= i; j += 4) {
                float4 m4 = *(const float4*)(mrow + j);
                s += m4.x * sv[(j + 0) * 192 + tid] + m4.y * sv[(j + 1) * 192 + tid]
                   + m4.z * sv[(j + 2) * 192 + tid] + m4.w * sv[(j + 3) * 192 + tid];
            }
            for (; j < i; j++) s += mrow[j] * sv[j * 192 + tid];
            sv[i * 192 + tid] -= s;
        } else if (tid < 288) {
            int c = tid - 192;
            float s = 0.f;
            const float* krow = sKK + i * 64;
            int j = 0;
            for (; j + 4 <= i; j += 4) {
                float4 m4 = *(const float4*)(krow + j);
                s += m4.x * skb[(j + 0) * 96 + c] + m4.y * skb[(j + 1) * 96 + c]
                   + m4.z * skb[(j + 2) * 96 + c] + m4.w * skb[(j + 3) * 96 + c];
            }
            for (; j < i; j++) s += krow[j] * skb[j * 96 + c];
            skb[i * 96 + c] -= s;
        }
        __syncthreads();
    }

    for (int i = tid; i < 12288; i += CP_THREADS) g_vh[cb192 + i] = sv[i];
    for (int i = tid; i < 6144; i += CP_THREADS) {
        int c = i / cDK;
        g_kce[cb96 + i] = skb[i] * expf(sdec[c]);
    }
    if (tid == 0) g_edl[cid] = expf(dl);
}

// ---------------- sequential scan over chunks ----------------
// grid (6, 16): x = 32-wide value-column split, y = bh; 512 threads
constexpr int SC_SMEM_FLOATS = 3 * 6144 + 4096 + 2048 + 2048 + 3072;
constexpr int SC_THREADS = 512;
__global__ void scan_kernel()
{
    extern __shared__ float sm[];
    float* sqe  = sm;
    float* skce = sqe + 6144;
    float* skd  = skce + 6144;
    float* sat  = skd + 6144;
    float* su   = sat + 4096;
    float* svn  = su + 2048;
    float* S    = svn + 2048;   // 96 x 32

    const int tid = threadIdx.x;
    const int bh = blockIdx.y;
    const int e0 = blockIdx.x * 32;
    const int e  = tid & 31;
    const int w  = tid >> 5;        // 0..15
    const int c0 = w * 4;           // 4 chunk rows per warp
    const int d0 = w * 6;           // 6 state rows per warp

    for (int i = tid; i < 3072; i += SC_THREADS) S[i] = 0.f;

    for (int n = 0; n < cNC; n++) {
        const size_t cbg = (size_t)bh * cL + n * cCS;
        const size_t cb96 = cbg * cDK;
        const size_t cb192 = cbg * cDV;
        __syncthreads();
        for (int i = tid; i < 1536; i += SC_THREADS) {
            ((float4*)sqe)[i]  = ((const float4*)(g_qn + cb96))[i];
            ((float4*)skce)[i] = ((const float4*)(g_kce + cb96))[i];
            ((float4*)skd)[i]  = ((const float4*)(g_kn + cb96))[i];
        }
        for (int i = tid; i < 1024; i += SC_THREADS)
            ((float4*)sat)[i] = ((const float4*)(g_at + (size_t)(bh * cNC + n) * 4096))[i];
        for (int i = tid; i < 512; i += SC_THREADS) {
            int c = i >> 3, ee = (i & 7) * 4;
            *(float4*)&su[c * 32 + ee] =
                *(const float4*)&g_vh[cb192 + (size_t)c * cDV + e0 + ee];
        }
        __syncthreads();

        // v_new = u - kce @ S
        float acc[4];
#pragma unroll
        for (int i = 0; i < 4; i++) acc[i] = 0.f;
        for (int j = 0; j < cDK; j += 4) {
            float s0 = S[(j + 0) * 32 + e];
            float s1 = S[(j + 1) * 32 + e];
            float s2 = S[(j + 2) * 32 + e];
            float s3 = S[(j + 3) * 32 + e];
#pragma unroll
            for (int i = 0; i < 4; i++) {
                float4 kv = *(const float4*)&skce[(c0 + i) * cDK + j];
                acc[i] += kv.x * s0 + kv.y * s1 + kv.z * s2 + kv.w * s3;
            }
        }
#pragma unroll
        for (int i = 0; i < 4; i++) svn[(c0 + i) * 32 + e] = su[(c0 + i) * 32 + e] - acc[i];
        __syncthreads();

        // o = qe @ S + attn @ v_new
#pragma unroll
        for (int i = 0; i < 4; i++) acc[i] = 0.f;
        for (int j = 0; j < cDK; j += 4) {
            float s0 = S[(j + 0) * 32 + e];
            float s1 = S[(j + 1) * 32 + e];
            float s2 = S[(j + 2) * 32 + e];
            float s3 = S[(j + 3) * 32 + e];
#pragma unroll
            for (int i = 0; i < 4; i++) {
                float4 qv = *(const float4*)&sqe[(c0 + i) * cDK + j];
                acc[i] += qv.x * s0 + qv.y * s1 + qv.z * s2 + qv.w * s3;
            }
        }
        for (int j = 0; j < 64; j += 4) {
            float v0 = svn[(j + 0) * 32 + e];
            float v1 = svn[(j + 1) * 32 + e];
            float v2 = svn[(j + 2) * 32 + e];
            float v3 = svn[(j + 3) * 32 + e];
#pragma unroll
            for (int i = 0; i < 4; i++) {
                float4 av = *(const float4*)&sat[(c0 + i) * 64 + j];
                acc[i] += av.x * v0 + av.y * v1 + av.z * v2 + av.w * v3;
            }
        }
#pragma unroll
        for (int i = 0; i < 4; i++)
            g_o[cb192 + (size_t)(c0 + i) * cDV + e0 + e] = acc[i];
        __syncthreads();

        // S = S*exp(dl) + kd^T @ v_new
        const float el = g_edl[bh * cNC + n];
        float accS[6];
#pragma unroll
        for (int ii = 0; ii < 6; ii++) accS[ii] = 0.f;
        for (int c = 0; c < 64; c++) {
            float v = svn[c * 32 + e];
            const float* kr = skd + c * cDK + d0;
            float2 k0 = *(const float2*)(kr);
            float2 k1 = *(const float2*)(kr + 2);
            float2 k2 = *(const float2*)(kr + 4);
            accS[0] += k0.x * v; accS[1] += k0.y * v;
            accS[2] += k1.x * v; accS[3] += k1.y * v;
            accS[4] += k2.x * v; accS[5] += k2.y * v;
        }
#pragma unroll
        for (int ii = 0; ii < 6; ii++) {
            int idx = (d0 + ii) * 32 + e;
            S[idx] = S[idx] * el + accS[ii];
        }
    }
}

// ---------------- gated RMS norm + transpose back (writes tf32 bits) ----------------
__global__ void gate_norm_kernel(const float* __restrict__ norm_w)
{
    int gw = (blockIdx.x * blockDim.x + threadIdx.x) >> 5;
    int lane = threadIdx.x & 31;
    if (gw >= cM * cH) return;
    int m = gw / cH, h = gw % cH;
    int b = m / cL, l = m % cL;
    const float* orow = g_o + ((size_t)(b * cH + h) * cL + l) * cDV;
    float vals[6];
    float ss = 0.f;
#pragma unroll
    for (int k = 0; k < 6; k++) {
        float v = orow[lane + 32 * k];
        vals[k] = v;
        ss += v * v;
    }
#pragma unroll
    for (int o = 16; o; o >>= 1) ss += __shfl_xor_sync(0xffffffffu, ss, o);
    float r = 1.f / sqrtf(ss / (float)cDV + 1e-5f);
#pragma unroll
    for (int k = 0; k < 6; k++) {
        int d = lane + 32 * k;
        float gg = g_proj[(size_t)m * cNP + 2 * cKD + cVD + h * cDV + d];
        float sg = gg / (1.f + expf(-gg));
        g_on[(size_t)m * cVD + h * cDV + d] = f2tf32(vals[k] * r * norm_w[d] * sg);
    }
}

// ---------------- host launch ----------------
template <typename T>
static T* sym(const void* symbol)
{
    void* p = nullptr;
    cudaGetSymbolAddress(&p, symbol);
    return (T*)p;
}

extern "C" void kernel_launch(void* const* d_in, const int* in_sizes, int n_in,
                              void* d_out, int out_size)
{
    const float* u       = (const float*)d_in[0];
    const float* Wq      = (const float*)d_in[1];
    const float* Wk      = (const float*)d_in[2];
    const float* Wv      = (const float*)d_in[3];
    const float* Wg      = (const float*)d_in[4];
    const float* Wo      = (const float*)d_in[5];
    const float* Wgk     = (const float*)d_in[6];
    const float* Wb      = (const float*)d_in[7];
    const float* b_b     = (const float*)d_in[8];
    const float* A_log   = (const float*)d_in[9];
    const float* dt_bias = (const float*)d_in[10];
    const float* conv_q  = (const float*)d_in[11];
    const float* conv_k  = (const float*)d_in[12];
    const float* conv_v  = (const float*)d_in[13];
    const float* norm_w  = (const float*)d_in[14];
    float* out = (float*)d_out;

    uint32_t* Wcat = sym<uint32_t>(g_Wcat);
    uint32_t* WoT  = sym<uint32_t>(g_WoT);
    uint32_t* uT   = sym<uint32_t>(g_uT);
    uint32_t* on   = sym<uint32_t>(g_on);
    float* proj = sym<float>(g_proj);

    cudaFuncSetAttribute(chunk_pre_kernel, cudaFuncAttributeMaxDynamicSharedMemorySize,
                         CP_SMEM_FLOATS * (int)sizeof(float));
    cudaFuncSetAttribute(scan_kernel, cudaFuncAttributeMaxDynamicSharedMemorySize,
                         SC_SMEM_FLOATS * (int)sizeof(float));
    cudaFuncSetAttribute(proj_gates_kernel, cudaFuncAttributeMaxDynamicSharedMemorySize, 65536);

    // 0-4: pack/convert + gates (launch #5 = big projection GEMM for ncu -s 5)
    pack_w_kernel<<<(cD * cNP + 255) / 256, 256>>>(Wq, Wk, Wv, Wg);
    pack_wo_kernel<<<(cVD * cD + 255) / 256, 256>>>(Wo);
    constexpr int UH = cM * cD / 2;
    convert_u_kernel<<<(UH + 255) / 256, 256>>>(u, 0, UH);
    convert_u_kernel<<<(UH + 255) / 256, 256>>>(u, UH, UH);
    proj_gates_kernel<<<cM / 8, 256, 65536>>>(u, Wgk, Wb, b_b, A_log, dt_bias);

    // 5: fused projection GEMM (q|k|v|g)
    gemm_tf32_kernel<<<dim3(cNP / 128, cM / 128), 256>>>(uT, cD, Wcat, cNP, proj, cNP, cM, cNP, cD);

    // 6: fused conv + silu for q,k,v
    conv_silu_kernel<<<(cM * 3072 + 255) / 256, 256>>>(conv_q, conv_k, conv_v);

    // 7-8: reshape / normalize
    l2norm_qk_kernel<<<(2 * cM * cH * 32 + 255) / 256, 256>>>();
    reshape_v_kernel<<<(cM * cVD + 255) / 256, 256>>>();

    // 9-10: delta-rule chunk precompute + scan
    chunk_pre_kernel<<<cBH * cNC, CP_THREADS, CP_SMEM_FLOATS * sizeof(float)>>>();
    scan_kernel<<<dim3(6, cBH), SC_THREADS, SC_SMEM_FLOATS * sizeof(float)>>>();

    // 11-12: gated rms norm + output projection
    gate_norm_kernel<<<(cM * cH * 32 + 255) / 256, 256>>>(norm_w);
    gemm_tf32_kernel<<<dim3(cD / 128, cM / 128), 256>>>(on, cVD, WoT, cD, out, cD, cM, cD, cVD);
}

// round 5
// speedup vs baseline: 1.9013x; 1.0575x over previous
#include <cuda_runtime.h>
#include <math.h>
#include <stdint.h>

// ---------------- problem constants ----------------
constexpr int cB  = 2;
constexpr int cL  = 4096;
constexpr int cD  = 1024;   // D_MODEL
constexpr int cKD = 768;    // KEY_DIM
constexpr int cVD = 1536;   // VALUE_DIM
constexpr int cH  = 8;
constexpr int cDK = 96;     // per-head qk dim
constexpr int cDV = 192;    // per-head v dim
constexpr int cCS = 64;     // chunk size
constexpr int cNC = cL / cCS;       // 64 chunks per sequence
constexpr int cM  = cB * cL;        // 8192 tokens
constexpr int cBH = cB * cH;        // 16
constexpr int cNP = cKD + cKD + cVD + cVD;  // 4608 packed projection width

// ---------------- scratch (device globals; no cudaMalloc allowed) ----------------
__device__ uint32_t g_Wcat[cD * cNP];   // packed [Wq|Wk|Wv|Wg], tf32 bits
__device__ uint32_t g_WoT [cVD * cD];   // Wo, tf32 bits
__device__ uint32_t g_uT  [cM * cD];    // u, tf32 bits
__device__ float g_proj[cM * cNP];      // packed projection outputs (fp32)
__device__ float g_qn [cM * cKD];   // head layout; becomes qe after chunk_pre
__device__ float g_kn [cM * cKD];   // head layout; becomes kd after chunk_pre
__device__ float g_vh [cM * cVD];   // head layout; becomes u_ after chunk_pre
__device__ float g_kce[cM * cKD];   // kcd * exp(dec)
__device__ float g_gk [cBH * cL];
__device__ float g_bt [cBH * cL];
__device__ float g_at [cBH * cNC * cCS * cCS];  // intra-chunk attn
__device__ float g_edl[cBH * cNC];
__device__ float g_o  [cM * cVD];   // (b,h,l,dv)
__device__ uint32_t g_on [cM * cVD];   // gated+normed, tf32 bits

// ---------------- tf32 helpers ----------------
__device__ __forceinline__ uint32_t f2tf32(float f)
{
    uint32_t r;
    asm("cvt.rna.tf32.f32 %0, %1;" : "=r"(r) : "f"(f));
    return r;
}

__device__ __forceinline__ void mma_tf32(float c[4], const uint32_t a[4], const uint32_t b[2])
{
    asm volatile(
        "mma.sync.aligned.m16n8k8.row.col.f32.tf32.tf32.f32 "
        "{%0,%1,%2,%3}, {%4,%5,%6,%7}, {%8,%9}, {%0,%1,%2,%3};"
        : "+f"(c[0]), "+f"(c[1]), "+f"(c[2]), "+f"(c[3])
        : "r"(a[0]), "r"(a[1]), "r"(a[2]), "r"(a[3]), "r"(b[0]), "r"(b[1]));
}

#define CP16(dst, src) \
    asm volatile("cp.async.cg.shared.global [%0], [%1], 16;" :: "r"(dst), "l"(src))

// ---------------- tf32 tensor-core GEMM (4-stage cp.async pipeline) ----------------
// C[M,N] = A[M,K] @ B[K,N], A/B already tf32 bit-patterns, row-major.
// M%128==0, N%128==0, K%16==0, K/16 >= 4. Dynamic smem: 75776 bytes.
constexpr int GEMM_SMEM = 4 * (128 * 20 + 16 * 136) * 4;
__global__ void __launch_bounds__(256, 2)
gemm_tf32_kernel(const uint32_t* __restrict__ A, int lda,
                 const uint32_t* __restrict__ B, int ldb,
                 float* __restrict__ C, int ldc,
                 int M, int N, int K)
{
    extern __shared__ uint32_t smem_u[];
    typedef uint32_t AsT[128][20];
    typedef uint32_t BsT[16][136];
    AsT* As = (AsT*)smem_u;                       // 4 stages, [m][k] stride 20
    BsT* Bs = (BsT*)(smem_u + 4 * 128 * 20);      // 4 stages, [k][n] stride 136

    const int tid  = threadIdx.x;
    const int wid  = tid >> 5;
    const int lane = tid & 31;
    const int g    = lane >> 2;
    const int t    = lane & 3;
    const int wm   = (wid >> 2) * 64;   // warp m offset
    const int wn   = (wid & 3) * 32;    // warp n offset

    const int bm = blockIdx.y * 128;
    const int bn = blockIdx.x * 128;

    const int arow = tid >> 1;           // 0..127
    const int akb  = (tid & 1) * 8;      // 0 or 8
    const int bkr  = tid >> 4;           // 0..15
    const int bnb  = (tid & 15) * 8;     // 0..120

    const uint32_t* Ag = A + (size_t)(bm + arow) * lda + akb;
    const uint32_t* Bg = B + (size_t)bkr * ldb + bn + bnb;

    uint32_t sa[4], sb[4];
#pragma unroll
    for (int s = 0; s < 4; s++) {
        sa[s] = (uint32_t)__cvta_generic_to_shared(&As[s][arow][akb]);
        sb[s] = (uint32_t)__cvta_generic_to_shared(&Bs[s][bkr][bnb]);
    }

    float acc[4][4][4];
#pragma unroll
    for (int i = 0; i < 4; i++)
#pragma unroll
        for (int j = 0; j < 4; j++)
#pragma unroll
            for (int r = 0; r < 4; r++) acc[i][j][r] = 0.f;

    const int nt = K >> 4;

    // prologue: stages 0..2
#pragma unroll
    for (int s = 0; s < 3; s++) {
        const uint32_t* a = Ag + (size_t)s * 16;
        const uint32_t* b = Bg + (size_t)s * 16 * ldb;
        CP16(sa[s], a); CP16(sa[s] + 16, a + 4);
        CP16(sb[s], b); CP16(sb[s] + 16, b + 4);
        asm volatile("cp.async.commit_group;");
    }

    for (int kt = 0; kt < nt; kt++) {
        asm volatile("cp.async.wait_group 2;");
        __syncthreads();

        const int buf = kt & 3;
#pragma unroll
        for (int ks = 0; ks < 16; ks += 8) {
            uint32_t af[4][4], bf[4][2];
#pragma unroll
            for (int mi = 0; mi < 4; mi++) {
                int mr = wm + mi * 16;
                af[mi][0] = As[buf][mr + g][ks + t];
                af[mi][1] = As[buf][mr + g + 8][ks + t];
                af[mi][2] = As[buf][mr + g][ks + t + 4];
                af[mi][3] = As[buf][mr + g + 8][ks + t + 4];
            }
#pragma unroll
            for (int ni = 0; ni < 4; ni++) {
                int nc = wn + ni * 8;
                bf[ni][0] = Bs[buf][ks + t][nc + g];
                bf[ni][1] = Bs[buf][ks + t + 4][nc + g];
            }
#pragma unroll
            for (int mi = 0; mi < 4; mi++)
#pragma unroll
                for (int ni = 0; ni < 4; ni++)
                    mma_tf32(acc[mi][ni], af[mi], bf[ni]);
        }

        if (kt + 3 < nt) {
            const int s = (kt + 3) & 3;
            const uint32_t* a = Ag + (size_t)(kt + 3) * 16;
            const uint32_t* b = Bg + (size_t)(kt + 3) * 16 * ldb;
            CP16(sa[s], a); CP16(sa[s] + 16, a + 4);
            CP16(sb[s], b); CP16(sb[s] + 16, b + 4);
        }
        asm volatile("cp.async.commit_group;");
    }

    // epilogue
#pragma unroll
    for (int mi = 0; mi < 4; mi++) {
#pragma unroll
        for (int ni = 0; ni < 4; ni++) {
            int row0 = bm + wm + mi * 16 + g;
            int col  = bn + wn + ni * 8 + 2 * t;
            *(float2*)(C + (size_t)row0 * ldc + col) = make_float2(acc[mi][ni][0], acc[mi][ni][1]);
            *(float2*)(C + (size_t)(row0 + 8) * ldc + col) = make_float2(acc[mi][ni][2], acc[mi][ni][3]);
        }
    }
}

// ---------------- pack [Wq|Wk|Wv|Wg] into one tf32 matrix ----------------
__global__ void pack_w_kernel(const float* __restrict__ Wq, const float* __restrict__ Wk,
                              const float* __restrict__ Wv, const float* __restrict__ Wg)
{
    int idx = blockIdx.x * blockDim.x + threadIdx.x;
    if (idx >= cD * cNP) return;
    int row = idx / cNP, col = idx % cNP;
    float v;
    if (col < cKD)            v = Wq[row * cKD + col];
    else if (col < 2 * cKD)   v = Wk[row * cKD + col - cKD];
    else if (col < 2 * cKD + cVD) v = Wv[row * cVD + col - 2 * cKD];
    else                      v = Wg[row * cVD + col - 2 * cKD - cVD];
    g_Wcat[idx] = f2tf32(v);
}

__global__ void pack_wo_kernel(const float* __restrict__ Wo)
{
    int idx = blockIdx.x * blockDim.x + threadIdx.x;
    if (idx >= cVD * cD) return;
    g_WoT[idx] = f2tf32(Wo[idx]);
}

__global__ void convert_u_kernel(const float4* __restrict__ u4)
{
    int idx = blockIdx.x * blockDim.x + threadIdx.x;
    if (idx >= cM * cD / 4) return;
    float4 v = u4[idx];
    uint4 r;
    r.x = f2tf32(v.x); r.y = f2tf32(v.y); r.z = f2tf32(v.z); r.w = f2tf32(v.w);
    ((uint4*)g_uT)[idx] = r;
}

// ---------------- gk / beta projections: warp per token, W in smem ----------------
__global__ void proj_gates_kernel(const float* __restrict__ u, const float* __restrict__ Wgk,
                                  const float* __restrict__ Wb, const float* __restrict__ b_b,
                                  const float* __restrict__ A_log, const float* __restrict__ dt_bias)
{
    extern __shared__ float sW[];   // [1024][16]
    const int tid = threadIdx.x;
    const int wid = tid >> 5;
    const int lane = tid & 31;

    for (int idx = tid; idx < cD * 16; idx += 256) {
        int i = idx >> 4, c = idx & 15;
        sW[idx] = (c < 8) ? Wgk[i * cH + c] : Wb[i * cH + (c - 8)];
    }
    __syncthreads();

    int m = blockIdx.x * 8 + wid;
    const float* ur = u + (size_t)m * cD;
    float s[16];
#pragma unroll
    for (int c = 0; c < 16; c++) s[c] = 0.f;
    for (int j = 0; j < 32; j++) {
        int i = lane + 32 * j;
        float uv = __ldg(ur + i);
        const float* wr = sW + i * 16;
#pragma unroll
        for (int c = 0; c < 16; c++) s[c] += uv * wr[c];
    }
#pragma unroll
    for (int c = 0; c < 16; c++) {
#pragma unroll
        for (int o = 16; o; o >>= 1) s[c] += __shfl_xor_sync(0xffffffffu, s[c], o);
    }
    if (lane < 8) {
        int h = lane;
        float x  = s[h] + dt_bias[h];
        float sp = (x > 20.f) ? x : log1pf(expf(x));
        float gkv = -expf(A_log[h]) * sp;
        int b = m / cL, l = m % cL;
        g_gk[((size_t)(b * cH + h)) * cL + l] = gkv;
    } else {
        int h = lane - 8;
        float bv = 1.f / (1.f + expf(-(s[8 + h] + b_b[h])));
        int b = m / cL, l = m % cL;
        g_bt[((size_t)(b * cH + h)) * cL + l] = bv;
    }
}

// ---------------- fused conv + SiLU + L2norm for q,k; writes head layout ----------------
// warp per (m, h): lane covers 3 channels of q and 3 of k.
__global__ void conv_qk_norm_kernel(const float* __restrict__ wq, const float* __restrict__ wk)
{
    int gw = (blockIdx.x * blockDim.x + threadIdx.x) >> 5;
    int lane = threadIdx.x & 31;
    if (gw >= cM * cH) return;
    int m = gw / cH, h = gw % cH;
    int b = m / cL, l = m % cL;
    const size_t rowbase = (size_t)(m - l) * cNP;

    float qv[3], kv[3];
    float ssq = 0.f, ssk = 0.f;
#pragma unroll
    for (int r = 0; r < 3; r++) {
        int c = h * cDK + lane + 32 * r;     // q column; k column = cKD + c
        float aq = 0.f, ak = 0.f;
#pragma unroll
        for (int j = 0; j < 4; j++) {
            int ll = l - 3 + j;
            if (ll >= 0) {
                const float* row = g_proj + rowbase + (size_t)ll * cNP;
                aq += row[c]       * wq[c * 4 + j];
                ak += row[cKD + c] * wk[c * 4 + j];
            }
        }
        aq = aq / (1.f + expf(-aq));
        ak = ak / (1.f + expf(-ak));
        qv[r] = aq; kv[r] = ak;
        ssq += aq * aq; ssk += ak * ak;
    }
#pragma unroll
    for (int o = 16; o; o >>= 1) {
        ssq += __shfl_xor_sync(0xffffffffu, ssq, o);
        ssk += __shfl_xor_sync(0xffffffffu, ssk, o);
    }
    float iq = 1.f / fmaxf(sqrtf(ssq), 1e-12f);
    float ik = 1.f / fmaxf(sqrtf(ssk), 1e-12f);
    float* dq = g_qn + ((size_t)(b * cH + h) * cL + l) * cDK;
    float* dk = g_kn + ((size_t)(b * cH + h) * cL + l) * cDK;
#pragma unroll
    for (int r = 0; r < 3; r++) {
        dq[lane + 32 * r] = qv[r] * iq;
        dk[lane + 32 * r] = kv[r] * ik;
    }
}

// ---------------- conv + SiLU for v; writes head layout directly ----------------
__global__ void conv_v_kernel(const float* __restrict__ wv)
{
    int idx = blockIdx.x * blockDim.x + threadIdx.x;
    if (idx >= cM * cVD) return;
    int c = idx % cVD;
    int m = idx / cVD;
    int l = m % cL, b = m / cL;
    float acc = 0.f;
#pragma unroll
    for (int j = 0; j < 4; j++) {
        int ll = l - 3 + j;
        if (ll >= 0) acc += g_proj[(size_t)(m - l + ll) * cNP + 2 * cKD + c] * wv[c * 4 + j];
    }
    int h = c / cDV, d = c % cDV;
    g_vh[((size_t)(b * cH + h) * cL + l) * cDV + d] = acc / (1.f + expf(-acc));
}

// ---------------- per-chunk precompute ----------------
constexpr int CP_SMEM_FLOATS = 3 * 6144 + 4096 + 4096 + 12288 + 64 + 64;
constexpr int CP_THREADS = 320;
__global__ void chunk_pre_kernel()
{
    extern __shared__ float sm[];
    float* sq   = sm;
    float* sk   = sq + 6144;
    float* skb  = sk + 6144;
    float* sKK  = skb + 6144;
    float* sM   = sKK + 4096;
    float* sv   = sM + 4096;
    float* sdec = sv + 12288;
    float* sbet = sdec + 64;

    const int tid = threadIdx.x;
    const int cid = blockIdx.x;           // 0..1023
    const int bh = cid / cNC;
    const int n  = cid % cNC;
    const size_t cbg  = (size_t)bh * cL + n * cCS;
    const size_t cb96  = cbg * cDK;
    const size_t cb192 = cbg * cDV;
    const float scale = rsqrtf((float)cDK);

    for (int i = tid; i < 1536; i += CP_THREADS) {
        ((float4*)sq)[i] = ((const float4*)(g_qn + cb96))[i];
        ((float4*)sk)[i] = ((const float4*)(g_kn + cb96))[i];
    }
    if (tid < 64) sbet[tid] = g_bt[cbg + tid];
    if (tid < 32) {
        float x0 = g_gk[cbg + tid], x1 = g_gk[cbg + 32 + tid];
#pragma unroll
        for (int o = 1; o < 32; o <<= 1) {
            float y = __shfl_up_sync(0xffffffffu, x0, o);
            if (tid >= o) x0 += y;
        }
        float t0 = __shfl_sync(0xffffffffu, x0, 31);
#pragma unroll
        for (int o = 1; o < 32; o <<= 1) {
            float y = __shfl_up_sync(0xffffffffu, x1, o);
            if (tid >= o) x1 += y;
        }
        sdec[tid] = x0;
        sdec[32 + tid] = x1 + t0;
    }
    __syncthreads();
    const float dl = sdec[63];

    for (int i = tid; i < 6144; i += CP_THREADS)  skb[i] = sk[i] * sbet[i / cDK];
    for (int i = tid; i < 12288; i += CP_THREADS) sv[i]  = g_vh[cb192 + i] * sbet[i / cDV];

    // write qe and kd back in place (shared copies keep originals)
    for (int i = tid; i < 6144; i += CP_THREADS) {
        int c = i / cDK;
        g_qn[cb96 + i] = sq[i] * scale * expf(sdec[c]);
        g_kn[cb96 + i] = sk[i] * expf(dl - sdec[c]);
    }
    __syncthreads();

    // KK = kb @ k^T
    for (int idx = tid; idx < 4096; idx += CP_THREADS) {
        int i = idx >> 6, j = idx & 63;
        float s = 0.f;
        const float4* a4 = (const float4*)(skb + i * cDK);
        const float4* b4 = (const float4*)(sk + j * cDK);
#pragma unroll 6
        for (int d = 0; d < cDK / 4; d++) {
            float4 a = a4[d], b = b4[d];
            s += a.x * b.x + a.y * b.y + a.z * b.z + a.w * b.w;
        }
        sKK[idx] = s;
    }
    // intra-chunk attn (incl diagonal)
    for (int idx = tid; idx < 4096; idx += CP_THREADS) {
        int i = idx >> 6, j = idx & 63;
        float a = 0.f;
        if (i >= j) {
            float s = 0.f;
            const float4* a4 = (const float4*)(sq + i * cDK);
            const float4* b4 = (const float4*)(sk + j * cDK);
#pragma unroll 6
            for (int d = 0; d < cDK / 4; d++) {
                float4 x = a4[d], y = b4[d];
                s += x.x * y.x + x.y * y.y + x.z * y.z + x.w * y.w;
            }
            a = s * scale * expf(sdec[i] - sdec[j]);
        }
        g_at[(size_t)cid * 4096 + idx] = a;
    }
    // M1 = KK * Lmask, strict lower
    for (int idx = tid; idx < 4096; idx += CP_THREADS) {
        int i = idx >> 6, j = idx & 63;
        sM[idx] = (i > j) ? sKK[idx] * expf(sdec[i] - sdec[j]) : 0.f;
    }
    __syncthreads();

    // concurrent forward substitutions
    for (int i = 1; i < 64; i++) {
        if (tid < 192) {
            float s = 0.f;
            const float* mrow = sM + i * 64;
            int j = 0;
            for (; j + 4 <= i; j += 4) {
                float4 m4 = *(const float4*)(mrow + j);
                s += m4.x * sv[(j + 0) * 192 + tid] + m4.y * sv[(j + 1) * 192 + tid]
                   + m4.z * sv[(j + 2) * 192 + tid] + m4.w * sv[(j + 3) * 192 + tid];
            }
            for (; j < i; j++) s += mrow[j] * sv[j * 192 + tid];
            sv[i * 192 + tid] -= s;
        } else if (tid < 288) {
            int c = tid - 192;
            float s = 0.f;
            const float* krow = sKK + i * 64;
            int j = 0;
            for (; j + 4 <= i; j += 4) {
                float4 m4 = *(const float4*)(krow + j);
                s += m4.x * skb[(j + 0) * 96 + c] + m4.y * skb[(j + 1) * 96 + c]
                   + m4.z * skb[(j + 2) * 96 + c] + m4.w * skb[(j + 3) * 96 + c];
            }
            for (; j < i; j++) s += krow[j] * skb[j * 96 + c];
            skb[i * 96 + c] -= s;
        }
        __syncthreads();
    }

    for (int i = tid; i < 12288; i += CP_THREADS) g_vh[cb192 + i] = sv[i];
    for (int i = tid; i < 6144; i += CP_THREADS) {
        int c = i / cDK;
        g_kce[cb96 + i] = skb[i] * expf(sdec[c]);
    }
    if (tid == 0) g_edl[cid] = expf(dl);
}

// ---------------- sequential scan over chunks ----------------
// grid (6, 16): x = 32-wide value-column split, y = bh; 512 threads
constexpr int SC_SMEM_FLOATS = 3 * 6144 + 4096 + 2048 + 2048 + 3072;
constexpr int SC_THREADS = 512;
__global__ void scan_kernel()
{
    extern __shared__ float sm[];
    float* sqe  = sm;
    float* skce = sqe + 6144;
    float* skd  = skce + 6144;
    float* sat  = skd + 6144;
    float* su   = sat + 4096;
    float* svn  = su + 2048;
    float* S    = svn + 2048;   // 96 x 32

    const int tid = threadIdx.x;
    const int bh = blockIdx.y;
    const int e0 = blockIdx.x * 32;
    const int e  = tid & 31;
    const int w  = tid >> 5;        // 0..15
    const int c0 = w * 4;           // 4 chunk rows per warp
    const int d0 = w * 6;           // 6 state rows per warp

    for (int i = tid; i < 3072; i += SC_THREADS) S[i] = 0.f;

    for (int n = 0; n < cNC; n++) {
        const size_t cbg = (size_t)bh * cL + n * cCS;
        const size_t cb96 = cbg * cDK;
        const size_t cb192 = cbg * cDV;
        __syncthreads();
        for (int i = tid; i < 1536; i += SC_THREADS) {
            ((float4*)sqe)[i]  = ((const float4*)(g_qn + cb96))[i];
            ((float4*)skce)[i] = ((const float4*)(g_kce + cb96))[i];
            ((float4*)skd)[i]  = ((const float4*)(g_kn + cb96))[i];
        }
        for (int i = tid; i < 1024; i += SC_THREADS)
            ((float4*)sat)[i] = ((const float4*)(g_at + (size_t)(bh * cNC + n) * 4096))[i];
        for (int i = tid; i < 512; i += SC_THREADS) {
            int c = i >> 3, ee = (i & 7) * 4;
            *(float4*)&su[c * 32 + ee] =
                *(const float4*)&g_vh[cb192 + (size_t)c * cDV + e0 + ee];
        }
        __syncthreads();

        // fused: v_new = u - kce@S  AND  o_part = qe@S (both read old S once)
        float accv[4], acco[4];
#pragma unroll
        for (int i = 0; i < 4; i++) { accv[i] = 0.f; acco[i] = 0.f; }
        for (int j = 0; j < cDK; j += 4) {
            float s0 = S[(j + 0) * 32 + e];
            float s1 = S[(j + 1) * 32 + e];
            float s2 = S[(j + 2) * 32 + e];
            float s3 = S[(j + 3) * 32 + e];
#pragma unroll
            for (int i = 0; i < 4; i++) {
                float4 kv = *(const float4*)&skce[(c0 + i) * cDK + j];
                float4 qv = *(const float4*)&sqe[(c0 + i) * cDK + j];
                accv[i] += kv.x * s0 + kv.y * s1 + kv.z * s2 + kv.w * s3;
                acco[i] += qv.x * s0 + qv.y * s1 + qv.z * s2 + qv.w * s3;
            }
        }
#pragma unroll
        for (int i = 0; i < 4; i++) svn[(c0 + i) * 32 + e] = su[(c0 + i) * 32 + e] - accv[i];
        __syncthreads();

        // o += attn @ v_new
        for (int j = 0; j < 64; j += 4) {
            float v0 = svn[(j + 0) * 32 + e];
            float v1 = svn[(j + 1) * 32 + e];
            float v2 = svn[(j + 2) * 32 + e];
            float v3 = svn[(j + 3) * 32 + e];
#pragma unroll
            for (int i = 0; i < 4; i++) {
                float4 av = *(const float4*)&sat[(c0 + i) * 64 + j];
                acco[i] += av.x * v0 + av.y * v1 + av.z * v2 + av.w * v3;
            }
        }
#pragma unroll
        for (int i = 0; i < 4; i++)
            g_o[cb192 + (size_t)(c0 + i) * cDV + e0 + e] = acco[i];
        __syncthreads();

        // S = S*exp(dl) + kd^T @ v_new
        const float el = g_edl[bh * cNC + n];
        float accS[6];
#pragma unroll
        for (int ii = 0; ii < 6; ii++) accS[ii] = 0.f;
        for (int c = 0; c < 64; c++) {
            float v = svn[c * 32 + e];
            const float* kr = skd + c * cDK + d0;
            float2 k0 = *(const float2*)(kr);
            float2 k1 = *(const float2*)(kr + 2);
            float2 k2 = *(const float2*)(kr + 4);
            accS[0] += k0.x * v; accS[1] += k0.y * v;
            accS[2] += k1.x * v; accS[3] += k1.y * v;
            accS[4] += k2.x * v; accS[5] += k2.y * v;
        }
#pragma unroll
        for (int ii = 0; ii < 6; ii++) {
            int idx = (d0 + ii) * 32 + e;
            S[idx] = S[idx] * el + accS[ii];
        }
    }
}

// ---------------- gated RMS norm + transpose back (writes tf32 bits) ----------------
__global__ void gate_norm_kernel(const float* __restrict__ norm_w)
{
    int gw = (blockIdx.x * blockDim.x + threadIdx.x) >> 5;
    int lane = threadIdx.x & 31;
    if (gw >= cM * cH) return;
    int m = gw / cH, h = gw % cH;
    int b = m / cL, l = m % cL;
    const float* orow = g_o + ((size_t)(b * cH + h) * cL + l) * cDV;
    float vals[6];
    float ss = 0.f;
#pragma unroll
    for (int k = 0; k < 6; k++) {
        float v = orow[lane + 32 * k];
        vals[k] = v;
        ss += v * v;
    }
#pragma unroll
    for (int o = 16; o; o >>= 1) ss += __shfl_xor_sync(0xffffffffu, ss, o);
    float r = 1.f / sqrtf(ss / (float)cDV + 1e-5f);
#pragma unroll
    for (int k = 0; k < 6; k++) {
        int d = lane + 32 * k;
        float gg = g_proj[(size_t)m * cNP + 2 * cKD + cVD + h * cDV + d];
        float sg = gg / (1.f + expf(-gg));
        g_on[(size_t)m * cVD + h * cDV + d] = f2tf32(vals[k] * r * norm_w[d] * sg);
    }
}

// ---------------- host launch ----------------
template <typename T>
static T* sym(const void* symbol)
{
    void* p = nullptr;
    cudaGetSymbolAddress(&p, symbol);
    return (T*)p;
}

extern "C" void kernel_launch(void* const* d_in, const int* in_sizes, int n_in,
                              void* d_out, int out_size)
{
    const float* u       = (const float*)d_in[0];
    const float* Wq      = (const float*)d_in[1];
    const float* Wk      = (const float*)d_in[2];
    const float* Wv      = (const float*)d_in[3];
    const float* Wg      = (const float*)d_in[4];
    const float* Wo      = (const float*)d_in[5];
    const float* Wgk     = (const float*)d_in[6];
    const float* Wb      = (const float*)d_in[7];
    const float* b_b     = (const float*)d_in[8];
    const float* A_log   = (const float*)d_in[9];
    const float* dt_bias = (const float*)d_in[10];
    const float* conv_q  = (const float*)d_in[11];
    const float* conv_k  = (const float*)d_in[12];
    const float* conv_v  = (const float*)d_in[13];
    const float* norm_w  = (const float*)d_in[14];
    float* out = (float*)d_out;

    uint32_t* Wcat = sym<uint32_t>(g_Wcat);
    uint32_t* WoT  = sym<uint32_t>(g_WoT);
    uint32_t* uT   = sym<uint32_t>(g_uT);
    uint32_t* on   = sym<uint32_t>(g_on);
    float* proj = sym<float>(g_proj);

    cudaFuncSetAttribute(gemm_tf32_kernel, cudaFuncAttributeMaxDynamicSharedMemorySize, GEMM_SMEM);
    cudaFuncSetAttribute(chunk_pre_kernel, cudaFuncAttributeMaxDynamicSharedMemorySize,
                         CP_SMEM_FLOATS * (int)sizeof(float));
    cudaFuncSetAttribute(scan_kernel, cudaFuncAttributeMaxDynamicSharedMemorySize,
                         SC_SMEM_FLOATS * (int)sizeof(float));
    cudaFuncSetAttribute(proj_gates_kernel, cudaFuncAttributeMaxDynamicSharedMemorySize, 65536);

    // pack/convert
    pack_w_kernel<<<(cD * cNP + 255) / 256, 256>>>(Wq, Wk, Wv, Wg);
    convert_u_kernel<<<(cM * cD / 4 + 255) / 256, 256>>>((const float4*)u);
    pack_wo_kernel<<<(cVD * cD + 255) / 256, 256>>>(Wo);

    // fused projection GEMM (q|k|v|g)
    gemm_tf32_kernel<<<dim3(cNP / 128, cM / 128), 256, GEMM_SMEM>>>(
        uT, cD, Wcat, cNP, proj, cNP, cM, cNP, cD);

    // gates
    proj_gates_kernel<<<cM / 8, 256, 65536>>>(u, Wgk, Wb, b_b, A_log, dt_bias);

    // fused conv+silu(+l2norm) -> head layouts
    conv_qk_norm_kernel<<<(cM * cH * 32 + 255) / 256, 256>>>(conv_q, conv_k);
    conv_v_kernel<<<(cM * cVD + 255) / 256, 256>>>(conv_v);

    // delta-rule chunk precompute + scan
    chunk_pre_kernel<<<cBH * cNC, CP_THREADS, CP_SMEM_FLOATS * sizeof(float)>>>();
    scan_kernel<<<dim3(6, cBH), SC_THREADS, SC_SMEM_FLOATS * sizeof(float)>>>();

    // gated rms norm + output projection
    gate_norm_kernel<<<(cM * cH * 32 + 255) / 256, 256>>>(norm_w);
    gemm_tf32_kernel<<<dim3(cD / 128, cM / 128), 256, GEMM_SMEM>>>(
        on, cVD, WoT, cD, out, cD, cM, cD, cVD);
}